// round 15
// baseline (speedup 1.0000x reference)
#include <cuda_runtime.h>
#include <cuda_bf16.h>
#include <math.h>
#include <stdint.h>

// Problem constants
#define BB 4
#define NT 96
#define CC 256
#define HH 8
#define DD 32
#define NN (NT*NT)          // 9216
#define MM (BB*NN)          // 36864
#define FIVEC (5*CC)        // 1280
#define DEPTH 4
#define SCALE_L2E (8.83883476483184405556f * 1.44269504088896340736f)

__device__ __forceinline__ float ex2f(float x) {
    float r; asm("ex2.approx.ftz.f32 %0, %1;" : "=f"(r) : "f"(x)); return r;
}

// ---------------- base-ISA tensor helpers (sm_80+) ----------------
__device__ __forceinline__ uint32_t smem_u32(const void* p) {
    uint32_t a;
    asm("{ .reg .u64 t; cvta.to.shared.u64 t, %1; cvt.u32.u64 %0, t; }" : "=r"(a) : "l"(p));
    return a;
}
__device__ __forceinline__ void cp_async16(uint32_t saddr, const void* gaddr) {
    asm volatile("cp.async.cg.shared.global [%0], [%1], 16;" :: "r"(saddr), "l"(gaddr));
}
__device__ __forceinline__ void cp_commit() {
    asm volatile("cp.async.commit_group;" ::: "memory");
}
template <int N>
__device__ __forceinline__ void cp_wait() {
    asm volatile("cp.async.wait_group %0;" :: "n"(N) : "memory");
}
__device__ __forceinline__ void ldsm_x4(uint32_t* r, uint32_t addr) {
    asm volatile("ldmatrix.sync.aligned.m8n8.x4.shared.b16 {%0,%1,%2,%3}, [%4];"
                 : "=r"(r[0]), "=r"(r[1]), "=r"(r[2]), "=r"(r[3]) : "r"(addr));
}
__device__ __forceinline__ void ldsm_x2(uint32_t* r, uint32_t addr) {
    asm volatile("ldmatrix.sync.aligned.m8n8.x2.shared.b16 {%0,%1}, [%2];"
                 : "=r"(r[0]), "=r"(r[1]) : "r"(addr));
}
__device__ __forceinline__ void mma16816(float* d, const uint32_t* a, const uint32_t* b) {
    asm volatile(
        "mma.sync.aligned.m16n8k16.row.col.f32.bf16.bf16.f32 "
        "{%0,%1,%2,%3}, {%4,%5,%6,%7}, {%8,%9}, {%0,%1,%2,%3};"
        : "+f"(d[0]), "+f"(d[1]), "+f"(d[2]), "+f"(d[3])
        : "r"(a[0]), "r"(a[1]), "r"(a[2]), "r"(a[3]), "r"(b[0]), "r"(b[1]));
}
__device__ __forceinline__ uint32_t sw128(uint32_t off) {
    return off ^ ((off >> 3) & 0x70);
}
__device__ __forceinline__ void sts128(uint32_t addr, uint32_t a, uint32_t b, uint32_t c, uint32_t d) {
    asm volatile("st.shared.v4.b32 [%0], {%1,%2,%3,%4};" :: "r"(addr), "r"(a), "r"(b), "r"(c), "r"(d));
}
__device__ __forceinline__ void sts32(uint32_t addr, uint32_t a) {
    asm volatile("st.shared.b32 [%0], %1;" :: "r"(addr), "r"(a));
}
__device__ __forceinline__ uint32_t pack_bf2(__nv_bfloat16 a, __nv_bfloat16 b) {
    return (uint32_t)__bfloat16_as_ushort(a) | ((uint32_t)__bfloat16_as_ushort(b) << 16);
}
__device__ __forceinline__ void split2(float a, float b, uint32_t& hi, uint32_t& lo) {
    __nv_bfloat16 h0 = __float2bfloat16(a), h1 = __float2bfloat16(b);
    __nv_bfloat16 l0 = __float2bfloat16(a - __bfloat162float(h0));
    __nv_bfloat16 l1 = __float2bfloat16(b - __bfloat162float(h1));
    hi = pack_bf2(h0, h1); lo = pack_bf2(l0, l1);
}
// packed element: hi bf16 in low half, lo bf16 in high half
__device__ __forceinline__ uint32_t elem_pack(float x) {
    __nv_bfloat16 h = __float2bfloat16(x);
    __nv_bfloat16 l = __float2bfloat16(x - __bfloat162float(h));
    return (uint32_t)__bfloat16_as_ushort(h) | ((uint32_t)__bfloat16_as_ushort(l) << 16);
}
// 8 packed words (read-only cache) -> hi/lo bf16x2 tiles (pure PRMT)
__device__ __forceinline__ void packtile8(const uint32_t* src, uint32_t hiaddr, uint32_t loaddr) {
    uint4 q0 = __ldg((const uint4*)src);
    uint4 q1 = __ldg((const uint4*)(src + 4));
    uint32_t e[8] = {q0.x,q0.y,q0.z,q0.w,q1.x,q1.y,q1.z,q1.w};
    uint32_t hw[4], lw[4];
    #pragma unroll
    for (int jj = 0; jj < 4; jj++) {
        hw[jj] = __byte_perm(e[2*jj], e[2*jj+1], 0x5410);
        lw[jj] = __byte_perm(e[2*jj], e[2*jj+1], 0x7632);
    }
    sts128(hiaddr, hw[0], hw[1], hw[2], hw[3]);
    sts128(loaddr, lw[0], lw[1], lw[2], lw[3]);
}

// ---------------- device global scratch ----------------
__device__ float g_bufA[MM*CC];
__device__ float g_bufB[MM*CC];
__device__ uint32_t g_qkv[MM*FIVEC];    // packed bf16 hi|lo per element
__device__ float g_S[BB*HH*NT*NN];      // s1: fp32 S1; s2 overwrites with packed bf16 A
__device__ float g_part[2*4096];
__device__ float g_ms[2];
__device__ float g_pool[BB*NT*CC];
__device__ int   g_isI64;
__device__ uint4 g_whi[DEPTH*10*4*1024];
__device__ uint4 g_wlo[DEPTH*10*4*1024];

// ---------------- adj dtype detection ----------------
__global__ void detect_adj_kern(const unsigned int* __restrict__ a, int n) {
    __shared__ int any;
    if (threadIdx.x == 0) any = 0;
    __syncthreads();
    int nz = 0;
    for (int i = 1 + 2*threadIdx.x; i < n; i += 2*blockDim.x)
        nz |= (a[i] != 0u);
    if (nz) any = 1;
    __syncthreads();
    if (threadIdx.x == 0) g_isI64 = any ? 0 : 1;
}

// ---------------- embedding gather ----------------
__global__ void embed_kern(const int* __restrict__ adj,
                           const float* __restrict__ emb,
                           float* __restrict__ X) {
    int i64 = g_isI64;
    int total = MM * (CC/4);
    for (int t = blockIdx.x*blockDim.x + threadIdx.x; t < total;
         t += gridDim.x*blockDim.x) {
        int m = t >> 6;
        int c4 = t & 63;
        int a = i64 ? adj[2*m] : adj[m];
        float4 v = ((const float4*)emb)[a*(CC/4) + c4];
        ((float4*)X)[m*(CC/4) + c4] = v;
    }
}

// ---------------- global mean/std reduction (float4 loads; layer 0 only) ----------------
__global__ void red1_kern(const float4* __restrict__ X) {
    float s = 0.f, s2 = 0.f;
    for (int i = blockIdx.x*blockDim.x + threadIdx.x; i < MM*CC/4;
         i += gridDim.x*blockDim.x) {
        float4 v = X[i];
        s  += (v.x + v.y) + (v.z + v.w);
        s2 += (v.x*v.x + v.y*v.y) + (v.z*v.z + v.w*v.w);
    }
    __shared__ float sh1[256], sh2[256];
    int t = threadIdx.x;
    sh1[t] = s; sh2[t] = s2;
    __syncthreads();
    for (int o = 128; o; o >>= 1) {
        if (t < o) { sh1[t] += sh1[t+o]; sh2[t] += sh2[t+o]; }
        __syncthreads();
    }
    if (t == 0) { g_part[blockIdx.x] = sh1[0]; g_part[4096 + blockIdx.x] = sh2[0]; }
}

__global__ void red2_kern(int n) {
    __shared__ double sh1[256], sh2[256];
    int t = threadIdx.x;
    double s = 0.0, s2 = 0.0;
    for (int i = t; i < n; i += 256) { s += (double)g_part[i]; s2 += (double)g_part[4096+i]; }
    sh1[t] = s; sh2[t] = s2;
    __syncthreads();
    for (int o = 128; o; o >>= 1) {
        if (t < o) { sh1[t] += sh1[t+o]; sh2[t] += sh2[t+o]; }
        __syncthreads();
    }
    if (t == 0) {
        double nn = (double)MM * (double)CC;
        double mean = sh1[0] / nn;
        double var  = (sh2[0] - sh1[0]*sh1[0]/nn) / (nn - 1.0);
        g_ms[0] = (float)mean;
        g_ms[1] = (float)(1.0 / sqrt(var));
    }
}

// ---------------- W conversion (once per call) ----------------
__global__ void convert_w_kern(const float* __restrict__ W) {
    int idx = blockIdx.x*blockDim.x + threadIdx.x;
    if (idx >= DEPTH*FIVEC*32) return;
    int l = idx / (FIVEC*32);
    int rem = idx % (FIVEC*32);
    int n = rem >> 5, k8 = rem & 31;
    const float4* src = (const float4*)(W + (size_t)l*FIVEC*CC + (size_t)n*CC + k8*8);
    float4 v0 = src[0], v1 = src[1];
    float v[8] = {v0.x,v0.y,v0.z,v0.w,v1.x,v1.y,v1.z,v1.w};
    uint32_t hw[4], lw[4];
    #pragma unroll
    for (int j = 0; j < 4; j++)
        split2(v[2*j], v[2*j+1], hw[j], lw[j]);
    int nt = n >> 7, r = n & 127, kc = k8 >> 3;
    uint32_t off = r*128 + (k8 & 7)*16;
    uint32_t sw = sw128(off);
    size_t tile = (size_t)((l*10 + nt)*4 + kc)*1024 + (sw >> 4);
    g_whi[tile] = make_uint4(hw[0], hw[1], hw[2], hw[3]);
    g_wlo[tile] = make_uint4(lw[0], lw[1], lw[2], lw[3]);
}

// ---------------- QKV GEMM: persistent A (fused norm+split once per row block) ----------------
// smem: AHI @0 (4 chunks x 16KB = 64KB), ALO @65536 (64KB),
//       B stages @131072 + s*32768 (Bhi 16KB + Blo 16KB per stage). Total 196608.
#define SM_QKV 196608
__global__ void __launch_bounds__(256, 1)
qkv_mma_kern(int layer, const float* __restrict__ X) {
    extern __shared__ char smem[];
    uint32_t sb = smem_u32(smem);
    int t = threadIdx.x, lane = t & 31, wid = t >> 5;
    int mt = blockIdx.x;
    int wm = wid & 1, wn = wid >> 1;
    float mean = g_ms[0], istd = g_ms[1];

    // Phase 1: convert A once (fp32 X -> norm -> split hi/lo, swizzled tiles)
    {
        int r = t >> 1, half = t & 1;
        const float* xrow = X + (size_t)(mt*128 + r)*CC + half*32;
        #pragma unroll
        for (int kc = 0; kc < 4; kc++) {
            #pragma unroll
            for (int it = 0; it < 4; it++) {
                const float* src = xrow + kc*64 + it*8;
                float4 v0 = *(const float4*)src;
                float4 v1 = *(const float4*)(src + 4);
                float v[8] = {v0.x,v0.y,v0.z,v0.w,v1.x,v1.y,v1.z,v1.w};
                uint32_t hw[4], lw[4];
                #pragma unroll
                for (int jj = 0; jj < 4; jj++)
                    split2((v[2*jj] - mean)*istd, (v[2*jj+1] - mean)*istd, hw[jj], lw[jj]);
                uint32_t off = (uint32_t)r*128 + (uint32_t)half*64 + (uint32_t)it*16;
                uint32_t sw = sw128(off);
                sts128(sb + kc*16384 + sw, hw[0], hw[1], hw[2], hw[3]);
                sts128(sb + 65536 + kc*16384 + sw, lw[0], lw[1], lw[2], lw[3]);
            }
        }
    }

    auto issueB = [&](int q) {              // q = nt*4 + kc, 0..39
        int s = q & 1;
        int nt2 = q >> 2, bkc = q & 3;
        const uint4* Hp = g_whi + (size_t)((layer*10 + nt2)*4 + bkc)*1024;
        const uint4* Lp = g_wlo + (size_t)((layer*10 + nt2)*4 + bkc)*1024;
        uint32_t sh = sb + 131072 + s*32768;
        #pragma unroll
        for (int i = 0; i < 4; i++)
            cp_async16(sh + (t + i*256)*16, Hp + t + i*256);
        uint32_t sl = sh + 16384;
        #pragma unroll
        for (int i = 0; i < 4; i++)
            cp_async16(sl + (t + i*256)*16, Lp + t + i*256);
        cp_commit();
    };

    issueB(0);
    __syncthreads();   // A tiles visible to all warps

    #pragma unroll 1
    for (int nt = 0; nt < 10; nt++) {
        float acc[4][4][4];
        #pragma unroll
        for (int a = 0; a < 4; a++)
            #pragma unroll
            for (int b = 0; b < 4; b++)
                #pragma unroll
                for (int c = 0; c < 4; c++) acc[a][b][c] = 0.f;

        #pragma unroll 1
        for (int kc = 0; kc < 4; kc++) {
            int q = nt*4 + kc;
            if (q < 39) { issueB(q + 1); cp_wait<1>(); }
            else        { cp_wait<0>(); }
            __syncthreads();
            uint32_t Bhib = sb + 131072 + (uint32_t)(q & 1)*32768;
            uint32_t Blob = Bhib + 16384;
            uint32_t Ahib = sb + kc*16384;
            uint32_t Alob = sb + 65536 + kc*16384;
            uint32_t pa[3] = {Ahib, Alob, Ahib};
            uint32_t pb[3] = {Bhib, Bhib, Blob};
            #pragma unroll
            for (int ps = 0; ps < 3; ps++) {
                uint32_t Ab = pa[ps], Bb = pb[ps];
                #pragma unroll
                for (int ks = 0; ks < 4; ks++) {
                    uint32_t afr[4][4];
                    #pragma unroll
                    for (int mf = 0; mf < 4; mf++) {
                        uint32_t off = (uint32_t)(wm*64 + mf*16 + (lane & 15))*128
                                     + ks*32 + (lane >> 4)*16;
                        ldsm_x4(afr[mf], Ab + sw128(off));
                    }
                    uint32_t bfr[4][2];
                    #pragma unroll
                    for (int nf = 0; nf < 4; nf++) {
                        uint32_t off = (uint32_t)(wn*32 + nf*8 + (lane & 7))*128
                                     + ks*32 + ((lane >> 3) & 1)*16;
                        ldsm_x2(bfr[nf], Bb + sw128(off));
                    }
                    #pragma unroll
                    for (int mf = 0; mf < 4; mf++)
                        #pragma unroll
                        for (int nf = 0; nf < 4; nf++)
                            mma16816(acc[mf][nf], afr[mf], bfr[nf]);
                }
            }
            __syncthreads();
        }
        int rbase = mt*128 + wm*64 + (lane >> 2);
        int cbase = nt*128 + wn*32 + (lane & 3)*2;
        #pragma unroll
        for (int mf = 0; mf < 4; mf++) {
            #pragma unroll
            for (int nf = 0; nf < 4; nf++) {
                size_t o0 = (size_t)(rbase + mf*16)*FIVEC + cbase + nf*8;
                *(uint2*)&g_qkv[o0] =
                    make_uint2(elem_pack(acc[mf][nf][0]), elem_pack(acc[mf][nf][1]));
                *(uint2*)&g_qkv[o0 + 8*FIVEC] =
                    make_uint2(elem_pack(acc[mf][nf][2]), elem_pack(acc[mf][nf][3]));
            }
        }
    }
}

// ================= tensor-core attention =================
__device__ __forceinline__ void qk_gemm_3pass(uint32_t sb, uint32_t AHI, uint32_t ALO,
                                              uint32_t BHI, uint32_t BLO,
                                              int lane, int wm, int wn,
                                              float acc[3][3][4]) {
    uint32_t pa[3] = {AHI, ALO, AHI};
    uint32_t pb[3] = {BHI, BHI, BLO};
    #pragma unroll
    for (int ps = 0; ps < 3; ps++) {
        uint32_t Ab = sb + pa[ps], Bb = sb + pb[ps];
        #pragma unroll
        for (int ks = 0; ks < 2; ks++) {
            uint32_t afr[3][4];
            #pragma unroll
            for (int mf = 0; mf < 3; mf++) {
                uint32_t off = (uint32_t)(wm*48 + mf*16 + (lane & 15))*128
                             + ks*32 + (lane >> 4)*16;
                ldsm_x4(afr[mf], Ab + sw128(off));
            }
            uint32_t bfr[3][2];
            #pragma unroll
            for (int nf = 0; nf < 3; nf++) {
                uint32_t off = (uint32_t)(wn*24 + nf*8 + (lane & 7))*128
                             + ks*32 + ((lane >> 3) & 1)*16;
                ldsm_x2(bfr[nf], Bb + sw128(off));
            }
            #pragma unroll
            for (int mf = 0; mf < 3; mf++)
                #pragma unroll
                for (int nf = 0; nf < 3; nf++)
                    mma16816(acc[mf][nf], afr[mf], bfr[nf]);
        }
    }
}

__device__ __forceinline__ void av_gemm_3pass(uint32_t sb,
                                              uint32_t AHI0, uint32_t AHI1,
                                              uint32_t ALO0, uint32_t ALO1,
                                              uint32_t VHI0, uint32_t VHI1,
                                              uint32_t VLO0, uint32_t VLO1,
                                              int lane, int wm, int wn,
                                              float acc2[3][4]) {
    uint32_t pa0[3] = {AHI0, ALO0, AHI0}, pa1[3] = {AHI1, ALO1, AHI1};
    uint32_t pv0[3] = {VHI0, VHI0, VLO0}, pv1[3] = {VHI1, VHI1, VLO1};
    #pragma unroll
    for (int ps = 0; ps < 3; ps++) {
        #pragma unroll
        for (int ch = 0; ch < 2; ch++) {
            uint32_t Ab = sb + (ch ? pa1[ps] : pa0[ps]);
            uint32_t Vb = sb + (ch ? pv1[ps] : pv0[ps]);
            int nks = ch ? 2 : 4;
            #pragma unroll
            for (int ks = 0; ks < 4; ks++) {
                if (ks >= nks) break;
                uint32_t afr[3][4];
                #pragma unroll
                for (int mf = 0; mf < 3; mf++) {
                    uint32_t off = (uint32_t)(wm*48 + mf*16 + (lane & 15))*128
                                 + ks*32 + (lane >> 4)*16;
                    ldsm_x4(afr[mf], Ab + sw128(off));
                }
                uint32_t bfr[2];
                {
                    uint32_t off = (uint32_t)(wn*8 + (lane & 7))*128
                                 + ks*32 + ((lane >> 3) & 1)*16;
                    ldsm_x2(bfr, Vb + sw128(off));
                }
                #pragma unroll
                for (int mf = 0; mf < 3; mf++)
                    mma16816(acc2[mf], afr[mf], bfr);
            }
        }
    }
}

// ---------------- s1: per (b,h,i) — S1 = Q·K1^T (fp32 out) ----------------
#define SM_S1 49152
__global__ void __launch_bounds__(256, 3)
s1_mma_kern() {
    extern __shared__ char smem[];
    uint32_t sb = smem_u32(smem);
    int t = threadIdx.x, lane = t & 31, wid = t >> 5;
    int wm = wid & 1, wn = wid >> 1;
    int bhi = blockIdx.x;
    int i = bhi % NT, bh = bhi / NT;
    int h = bh % HH, b = bh / HH;
    int baseQ = (b*NN + i*NT)*FIVEC + h*DD;
    int baseK = baseQ + CC;
    for (int idx = t; idx < 384; idx += 256) {
        int r = idx >> 2, g = idx & 3;
        uint32_t sw = sw128((uint32_t)(r*128 + g*16));
        packtile8(g_qkv + baseQ + (size_t)r*FIVEC + g*8, sb + sw,         sb + 12288 + sw);
        packtile8(g_qkv + baseK + (size_t)r*FIVEC + g*8, sb + 24576 + sw, sb + 36864 + sw);
    }
    __syncthreads();
    float acc[3][3][4];
    #pragma unroll
    for (int a = 0; a < 3; a++)
        #pragma unroll
        for (int bq = 0; bq < 3; bq++)
            #pragma unroll
            for (int c = 0; c < 4; c++) acc[a][bq][c] = 0.f;
    qk_gemm_3pass(sb, 0, 12288, 24576, 36864, lane, wm, wn, acc);
    size_t base = (size_t)(bh*NT + i) * NN;
    int rbase = wm*48 + (lane >> 2);
    int cbase = wn*24 + (lane & 3)*2;
    #pragma unroll
    for (int mf = 0; mf < 3; mf++) {
        #pragma unroll
        for (int nf = 0; nf < 3; nf++) {
            int row = rbase + mf*16, col = cbase + nf*8;
            *(float2*)&g_S[base + (size_t)row*NT + col]     = make_float2(acc[mf][nf][0], acc[mf][nf][1]);
            *(float2*)&g_S[base + (size_t)(row+8)*NT + col] = make_float2(acc[mf][nf][2], acc[mf][nf][3]);
        }
    }
}

// ---------------- s2: per (b,h,j) — GEMM1 + register softmax + packed A + A·V2 GEMM ----------------
#define SM_S2M 68608
__global__ void __launch_bounds__(256, 3)
s2_mma_kern(float* __restrict__ Xout) {
    extern __shared__ char smem[];
    uint32_t sb = smem_u32(smem);
    float* redmax = (float*)(smem + 65536);
    float* redsum = (float*)(smem + 67072);
    int t = threadIdx.x, lane = t & 31, wid = t >> 5;
    int wm = wid & 1, wn = wid >> 1;
    int bhj = blockIdx.x;
    int j = bhj % NT, bh = bhj / NT;
    int h = bh % HH, b = bh / HH;
    int baseQ = (b*NN + j)*FIVEC + h*DD;
    int baseK2 = baseQ + 2*CC;
    int baseV2 = baseQ + 4*CC;

    for (int idx = t; idx < 384; idx += 256) {
        int r = idx >> 2, g = idx & 3;
        uint32_t sw = sw128((uint32_t)(r*128 + g*16));
        packtile8(g_qkv + baseQ  + (size_t)r*NT*FIVEC + g*8, sb + sw,         sb + 12288 + sw);
        packtile8(g_qkv + baseK2 + (size_t)r*NT*FIVEC + g*8, sb + 24576 + sw, sb + 36864 + sw);
    }
    for (int idx = t; idx < 48*32; idx += 256) {
        int d = idx & 31, pp = idx >> 5;
        int p = pp*2;
        uint32_t e0 = __ldg(&g_qkv[baseV2 + (size_t)p*NT*FIVEC + d]);
        uint32_t e1 = __ldg(&g_qkv[baseV2 + (size_t)(p+1)*NT*FIVEC + d]);
        uint32_t hw = __byte_perm(e0, e1, 0x5410);
        uint32_t lw = __byte_perm(e0, e1, 0x7632);
        uint32_t hbase = (p < 64) ? 49152u : 53248u;
        uint32_t lbase = (p < 64) ? 57344u : 61440u;
        uint32_t off = (uint32_t)d*128 + (uint32_t)((p < 64) ? p : p - 64)*2;
        uint32_t sw = sw128(off);
        sts32(sb + hbase + sw, hw);
        sts32(sb + lbase + sw, lw);
    }
    __syncthreads();
    float acc[3][3][4];
    #pragma unroll
    for (int a = 0; a < 3; a++)
        #pragma unroll
        for (int bq = 0; bq < 3; bq++)
            #pragma unroll
            for (int c = 0; c < 4; c++) acc[a][bq][c] = 0.f;
    qk_gemm_3pass(sb, 0, 12288, 24576, 36864, lane, wm, wn, acc);

    size_t sBase = (size_t)bh * NT * NN + (size_t)j * NT;
    int rbase = wm*48 + (lane >> 2);
    int cbase = wn*24 + (lane & 3)*2;
    #pragma unroll
    for (int mf = 0; mf < 3; mf++) {
        int r0 = rbase + mf*16;
        #pragma unroll
        for (int nf = 0; nf < 3; nf++) {
            int col = cbase + nf*8;
            float2 s1a = __ldg((const float2*)&g_S[sBase + (size_t)r0*NN + col]);
            float2 s1b = __ldg((const float2*)&g_S[sBase + (size_t)(r0+8)*NN + col]);
            acc[mf][nf][0] = (acc[mf][nf][0] + s1a.x) * SCALE_L2E;
            acc[mf][nf][1] = (acc[mf][nf][1] + s1a.y) * SCALE_L2E;
            acc[mf][nf][2] = (acc[mf][nf][2] + s1b.x) * SCALE_L2E;
            acc[mf][nf][3] = (acc[mf][nf][3] + s1b.y) * SCALE_L2E;
        }
    }
    float m0[3], m1[3];
    #pragma unroll
    for (int mf = 0; mf < 3; mf++) {
        m0[mf] = -1e30f; m1[mf] = -1e30f;
        #pragma unroll
        for (int nf = 0; nf < 3; nf++) {
            m0[mf] = fmaxf(m0[mf], fmaxf(acc[mf][nf][0], acc[mf][nf][1]));
            m1[mf] = fmaxf(m1[mf], fmaxf(acc[mf][nf][2], acc[mf][nf][3]));
        }
        m0[mf] = fmaxf(m0[mf], __shfl_xor_sync(0xffffffffu, m0[mf], 1));
        m0[mf] = fmaxf(m0[mf], __shfl_xor_sync(0xffffffffu, m0[mf], 2));
        m1[mf] = fmaxf(m1[mf], __shfl_xor_sync(0xffffffffu, m1[mf], 1));
        m1[mf] = fmaxf(m1[mf], __shfl_xor_sync(0xffffffffu, m1[mf], 2));
    }
    if ((lane & 3) == 0) {
        #pragma unroll
        for (int mf = 0; mf < 3; mf++) {
            int r0 = rbase + mf*16;
            redmax[r0*4 + wn]     = m0[mf];
            redmax[(r0+8)*4 + wn] = m1[mf];
        }
    }
    __syncthreads();
    float s0[3], s1[3];
    #pragma unroll
    for (int mf = 0; mf < 3; mf++) {
        int r0 = rbase + mf*16;
        float rm0 = fmaxf(fmaxf(redmax[r0*4], redmax[r0*4+1]),
                          fmaxf(redmax[r0*4+2], redmax[r0*4+3]));
        float rm1 = fmaxf(fmaxf(redmax[(r0+8)*4], redmax[(r0+8)*4+1]),
                          fmaxf(redmax[(r0+8)*4+2], redmax[(r0+8)*4+3]));
        s0[mf] = 0.f; s1[mf] = 0.f;
        #pragma unroll
        for (int nf = 0; nf < 3; nf++) {
            acc[mf][nf][0] = ex2f(acc[mf][nf][0] - rm0);
            acc[mf][nf][1] = ex2f(acc[mf][nf][1] - rm0);
            acc[mf][nf][2] = ex2f(acc[mf][nf][2] - rm1);
            acc[mf][nf][3] = ex2f(acc[mf][nf][3] - rm1);
            s0[mf] += acc[mf][nf][0] + acc[mf][nf][1];
            s1[mf] += acc[mf][nf][2] + acc[mf][nf][3];
        }
        s0[mf] += __shfl_xor_sync(0xffffffffu, s0[mf], 1);
        s0[mf] += __shfl_xor_sync(0xffffffffu, s0[mf], 2);
        s1[mf] += __shfl_xor_sync(0xffffffffu, s1[mf], 1);
        s1[mf] += __shfl_xor_sync(0xffffffffu, s1[mf], 2);
    }
    if ((lane & 3) == 0) {
        #pragma unroll
        for (int mf = 0; mf < 3; mf++) {
            int r0 = rbase + mf*16;
            redsum[r0*4 + wn]     = s0[mf];
            redsum[(r0+8)*4 + wn] = s1[mf];
        }
    }
    __syncthreads();
    uint2* gS2 = (uint2*)g_S;
    #pragma unroll
    for (int mf = 0; mf < 3; mf++) {
        int r0 = rbase + mf*16;
        float inv0 = 1.f / ((redsum[r0*4] + redsum[r0*4+1]) +
                            (redsum[r0*4+2] + redsum[r0*4+3]));
        float inv1 = 1.f / ((redsum[(r0+8)*4] + redsum[(r0+8)*4+1]) +
                            (redsum[(r0+8)*4+2] + redsum[(r0+8)*4+3]));
        #pragma unroll
        for (int nf = 0; nf < 3; nf++) {
            int col = cbase + nf*8;
            uint32_t e0 = elem_pack(acc[mf][nf][0]*inv0);
            uint32_t e1 = elem_pack(acc[mf][nf][1]*inv0);
            uint32_t e2 = elem_pack(acc[mf][nf][2]*inv1);
            uint32_t e3 = elem_pack(acc[mf][nf][3]*inv1);
            gS2[(sBase + (size_t)r0*NN + col) >> 1]     = make_uint2(e0, e1);
            gS2[(sBase + (size_t)(r0+8)*NN + col) >> 1] = make_uint2(e2, e3);
            int ch = col < 64;
            uint32_t hb = ch ? 0u : 12288u;
            uint32_t lb = ch ? 24576u : 36864u;
            uint32_t off0 = (uint32_t)r0*128 + (uint32_t)(ch ? col : col - 64)*2;
            uint32_t off1 = off0 + 1024;
            sts32(sb + hb + sw128(off0), __byte_perm(e0, e1, 0x5410));
            sts32(sb + lb + sw128(off0), __byte_perm(e0, e1, 0x7632));
            sts32(sb + hb + sw128(off1), __byte_perm(e2, e3, 0x5410));
            sts32(sb + lb + sw128(off1), __byte_perm(e2, e3, 0x7632));
        }
    }
    __syncthreads();
    float acc2[3][4];
    #pragma unroll
    for (int a = 0; a < 3; a++)
        #pragma unroll
        for (int c = 0; c < 4; c++) acc2[a][c] = 0.f;
    av_gemm_3pass(sb, 0, 12288, 24576, 36864, 49152, 53248, 57344, 61440,
                  lane, wm, wn, acc2);
    {
        int col = wn*8 + (lane & 3)*2;
        #pragma unroll
        for (int mf = 0; mf < 3; mf++) {
            int row = rbase + mf*16;
            size_t o0 = (size_t)(b*NN + row*NT + j)*CC + h*DD + col;
            size_t o1 = (size_t)(b*NN + (row+8)*NT + j)*CC + h*DD + col;
            *(float2*)&Xout[o0] = make_float2(acc2[mf][0], acc2[mf][1]);
            *(float2*)&Xout[o1] = make_float2(acc2[mf][2], acc2[mf][3]);
        }
    }
}

// ---------------- o1: per (b,h,i) — O1 = A·V1 + RMW Xout + fused norm stats ----------------
#define SM_O1M 65536
__global__ void __launch_bounds__(256, 3)
o1_mma_kern(float* __restrict__ Xout) {
    extern __shared__ char smem[];
    uint32_t sb = smem_u32(smem);
    int t = threadIdx.x, lane = t & 31, wid = t >> 5;
    int wm = wid & 1, wn = wid >> 1;
    int bhi = blockIdx.x;
    int i = bhi % NT, bh = bhi / NT;
    int h = bh % HH, b = bh / HH;
    size_t aBase = (size_t)(bh*NT + i) * NN;
    int baseV = (b*NN + i*NT)*FIVEC + 3*CC + h*DD;

    const uint32_t* gS32 = (const uint32_t*)g_S;
    for (int idx = t; idx < 96*12; idx += 256) {
        int r = idx / 12, g = idx % 12;
        uint32_t hbase = (g < 8) ? 0u : 12288u;
        uint32_t lbase = (g < 8) ? 24576u : 36864u;
        uint32_t off = (uint32_t)r*128 + (uint32_t)((g < 8) ? g : g - 8)*16;
        uint32_t sw = sw128(off);
        packtile8(gS32 + aBase + (size_t)r*NT + g*8, sb + hbase + sw, sb + lbase + sw);
    }
    for (int idx = t; idx < 48*32; idx += 256) {
        int d = idx & 31, pp = idx >> 5;
        int p = pp*2;
        uint32_t e0 = __ldg(&g_qkv[baseV + (size_t)p*FIVEC + d]);
        uint32_t e1 = __ldg(&g_qkv[baseV + (size_t)(p+1)*FIVEC + d]);
        uint32_t hw = __byte_perm(e0, e1, 0x5410);
        uint32_t lw = __byte_perm(e0, e1, 0x7632);
        uint32_t hbase = (p < 64) ? 49152u : 53248u;
        uint32_t lbase = (p < 64) ? 57344u : 61440u;
        uint32_t off = (uint32_t)d*128 + (uint32_t)((p < 64) ? p : p - 64)*2;
        uint32_t sw = sw128(off);
        sts32(sb + hbase + sw, hw);
        sts32(sb + lbase + sw, lw);
    }
    __syncthreads();
    float acc2[3][4];
    #pragma unroll
    for (int a = 0; a < 3; a++)
        #pragma unroll
        for (int c = 0; c < 4; c++) acc2[a][c] = 0.f;
    av_gemm_3pass(sb, 0, 12288, 24576, 36864, 49152, 53248, 57344, 61440,
                  lane, wm, wn, acc2);
    float ps = 0.f, ps2 = 0.f;
    {
        int rbase = wm*48 + (lane >> 2);
        int col = wn*8 + (lane & 3)*2;
        #pragma unroll
        for (int mf = 0; mf < 3; mf++) {
            int row = rbase + mf*16;   // j
            size_t o0 = (size_t)(b*NN + i*NT + row)*CC + h*DD + col;
            size_t o1 = (size_t)(b*NN + i*NT + row + 8)*CC + h*DD + col;
            float2 a0 = *(const float2*)&Xout[o0];
            float2 a1 = *(const float2*)&Xout[o1];
            float f0 = a0.x + acc2[mf][0], f1 = a0.y + acc2[mf][1];
            float f2 = a1.x + acc2[mf][2], f3 = a1.y + acc2[mf][3];
            *(float2*)&Xout[o0] = make_float2(f0, f1);
            *(float2*)&Xout[o1] = make_float2(f2, f3);
            ps  += (f0 + f1) + (f2 + f3);
            ps2 += (f0*f0 + f1*f1) + (f2*f2 + f3*f3);
        }
    }
    __syncthreads();
    float* red = (float*)smem;
    red[t] = ps; red[256 + t] = ps2;
    __syncthreads();
    #pragma unroll
    for (int o = 128; o; o >>= 1) {
        if (t < o) { red[t] += red[t+o]; red[256+t] += red[256+t+o]; }
        __syncthreads();
    }
    if (t == 0) {
        g_part[blockIdx.x]        = red[0];
        g_part[4096 + blockIdx.x] = red[256];
    }
}

// ---------------- pooling + head ----------------
__global__ void pool1_kern(const float* __restrict__ X) {
    int bi = blockIdx.x;
    int b = bi / NT, i = bi % NT;
    int c = threadIdx.x;
    float s = 0.f;
    for (int j = 0; j < NT; j++)
        s += X[(size_t)(b*NN + i*NT + j)*CC + c];
    g_pool[bi*CC + c] = s;
}

__global__ void pool2_head_kern(const float* __restrict__ W,
                                const float* __restrict__ bias,
                                float* __restrict__ out) {
    int b = blockIdx.x;
    __shared__ float xb[CC];
    int c = threadIdx.x;
    float s = 0.f;
    for (int i = 0; i < NT; i++)
        s += g_pool[(b*NT + i)*CC + c];
    xb[c] = s * (1.f / (float)NN);
    __syncthreads();
    float acc = bias[c];
    #pragma unroll 8
    for (int ci = 0; ci < CC; ci++)
        acc += xb[ci] * W[c*CC + ci];
    out[b*CC + c] = acc;
}

// ---------------- launch ----------------
extern "C" void kernel_launch(void* const* d_in, const int* in_sizes, int n_in,
                              void* d_out, int out_size) {
    const int*   adj   = (const int*)d_in[0];
    const float* emb   = (const float*)d_in[1];
    const float* qkvw  = (const float*)d_in[2];
    const float* headw = (const float*)d_in[3];
    const float* headb = (const float*)d_in[4];
    float* out = (float*)d_out;

    float *bufA, *bufB;
    cudaGetSymbolAddress((void**)&bufA, g_bufA);
    cudaGetSymbolAddress((void**)&bufB, g_bufB);

    cudaFuncSetAttribute(qkv_mma_kern, cudaFuncAttributeMaxDynamicSharedMemorySize, SM_QKV);
    cudaFuncSetAttribute(s1_mma_kern,  cudaFuncAttributeMaxDynamicSharedMemorySize, SM_S1);
    cudaFuncSetAttribute(s2_mma_kern,  cudaFuncAttributeMaxDynamicSharedMemorySize, SM_S2M);
    cudaFuncSetAttribute(o1_mma_kern,  cudaFuncAttributeMaxDynamicSharedMemorySize, SM_O1M);

    detect_adj_kern<<<1, 256>>>((const unsigned int*)adj, BB*NN);
    embed_kern<<<1024, 256>>>(adj, emb, bufA);
    convert_w_kern<<<(DEPTH*FIVEC*32 + 255)/256, 256>>>(qkvw);

    for (int l = 0; l < DEPTH; l++) {
        float* cur = (l & 1) ? bufB : bufA;
        float* nxt = (l & 1) ? bufA : bufB;
        if (l == 0) {
            red1_kern<<<1024, 256>>>((const float4*)cur);
            red2_kern<<<1, 256>>>(1024);
        } else {
            red2_kern<<<1, 256>>>(BB*HH*NT);   // partials from previous o1
        }
        qkv_mma_kern<<<MM/128, 256, SM_QKV>>>(l, cur);
        s1_mma_kern<<<BB*HH*NT, 256, SM_S1>>>();
        s2_mma_kern<<<BB*HH*NT, 256, SM_S2M>>>(nxt);
        o1_mma_kern<<<BB*HH*NT, 256, SM_O1M>>>(nxt);
    }
    pool1_kern<<<BB*NT, 256>>>(bufA);
    pool2_head_kern<<<BB, 256>>>(headw, headb, out);
}

// round 16
// speedup vs baseline: 1.0883x; 1.0883x over previous
#include <cuda_runtime.h>
#include <cuda_bf16.h>
#include <math.h>
#include <stdint.h>

// Problem constants
#define BB 4
#define NT 96
#define CC 256
#define HH 8
#define DD 32
#define NN (NT*NT)          // 9216
#define MM (BB*NN)          // 36864
#define FIVEC (5*CC)        // 1280
#define DEPTH 4
#define SCALE_L2E (8.83883476483184405556f * 1.44269504088896340736f)

__device__ __forceinline__ float ex2f(float x) {
    float r; asm("ex2.approx.ftz.f32 %0, %1;" : "=f"(r) : "f"(x)); return r;
}

// ---------------- base-ISA tensor helpers (sm_80+) ----------------
__device__ __forceinline__ uint32_t smem_u32(const void* p) {
    uint32_t a;
    asm("{ .reg .u64 t; cvta.to.shared.u64 t, %1; cvt.u32.u64 %0, t; }" : "=r"(a) : "l"(p));
    return a;
}
__device__ __forceinline__ void cp_async16(uint32_t saddr, const void* gaddr) {
    asm volatile("cp.async.cg.shared.global [%0], [%1], 16;" :: "r"(saddr), "l"(gaddr));
}
__device__ __forceinline__ void cp_commit() {
    asm volatile("cp.async.commit_group;" ::: "memory");
}
template <int N>
__device__ __forceinline__ void cp_wait() {
    asm volatile("cp.async.wait_group %0;" :: "n"(N) : "memory");
}
__device__ __forceinline__ void ldsm_x4(uint32_t* r, uint32_t addr) {
    asm volatile("ldmatrix.sync.aligned.m8n8.x4.shared.b16 {%0,%1,%2,%3}, [%4];"
                 : "=r"(r[0]), "=r"(r[1]), "=r"(r[2]), "=r"(r[3]) : "r"(addr));
}
__device__ __forceinline__ void ldsm_x2(uint32_t* r, uint32_t addr) {
    asm volatile("ldmatrix.sync.aligned.m8n8.x2.shared.b16 {%0,%1}, [%2];"
                 : "=r"(r[0]), "=r"(r[1]) : "r"(addr));
}
__device__ __forceinline__ void mma16816(float* d, const uint32_t* a, const uint32_t* b) {
    asm volatile(
        "mma.sync.aligned.m16n8k16.row.col.f32.bf16.bf16.f32 "
        "{%0,%1,%2,%3}, {%4,%5,%6,%7}, {%8,%9}, {%0,%1,%2,%3};"
        : "+f"(d[0]), "+f"(d[1]), "+f"(d[2]), "+f"(d[3])
        : "r"(a[0]), "r"(a[1]), "r"(a[2]), "r"(a[3]), "r"(b[0]), "r"(b[1]));
}
__device__ __forceinline__ uint32_t sw128(uint32_t off) {
    return off ^ ((off >> 3) & 0x70);
}
__device__ __forceinline__ void sts128(uint32_t addr, uint32_t a, uint32_t b, uint32_t c, uint32_t d) {
    asm volatile("st.shared.v4.b32 [%0], {%1,%2,%3,%4};" :: "r"(addr), "r"(a), "r"(b), "r"(c), "r"(d));
}
__device__ __forceinline__ void sts32(uint32_t addr, uint32_t a) {
    asm volatile("st.shared.b32 [%0], %1;" :: "r"(addr), "r"(a));
}
__device__ __forceinline__ uint32_t pack_bf2(__nv_bfloat16 a, __nv_bfloat16 b) {
    return (uint32_t)__bfloat16_as_ushort(a) | ((uint32_t)__bfloat16_as_ushort(b) << 16);
}
__device__ __forceinline__ void split2(float a, float b, uint32_t& hi, uint32_t& lo) {
    __nv_bfloat16 h0 = __float2bfloat16(a), h1 = __float2bfloat16(b);
    __nv_bfloat16 l0 = __float2bfloat16(a - __bfloat162float(h0));
    __nv_bfloat16 l1 = __float2bfloat16(b - __bfloat162float(h1));
    hi = pack_bf2(h0, h1); lo = pack_bf2(l0, l1);
}
// packed element: hi bf16 in low half, lo bf16 in high half
__device__ __forceinline__ uint32_t elem_pack(float x) {
    __nv_bfloat16 h = __float2bfloat16(x);
    __nv_bfloat16 l = __float2bfloat16(x - __bfloat162float(h));
    return (uint32_t)__bfloat16_as_ushort(h) | ((uint32_t)__bfloat16_as_ushort(l) << 16);
}
// 8 packed words (read-only cache) -> hi/lo bf16x2 tiles (pure PRMT)
__device__ __forceinline__ void packtile8(const uint32_t* src, uint32_t hiaddr, uint32_t loaddr) {
    uint4 q0 = __ldg((const uint4*)src);
    uint4 q1 = __ldg((const uint4*)(src + 4));
    uint32_t e[8] = {q0.x,q0.y,q0.z,q0.w,q1.x,q1.y,q1.z,q1.w};
    uint32_t hw[4], lw[4];
    #pragma unroll
    for (int jj = 0; jj < 4; jj++) {
        hw[jj] = __byte_perm(e[2*jj], e[2*jj+1], 0x5410);
        lw[jj] = __byte_perm(e[2*jj], e[2*jj+1], 0x7632);
    }
    sts128(hiaddr, hw[0], hw[1], hw[2], hw[3]);
    sts128(loaddr, lw[0], lw[1], lw[2], lw[3]);
}

// ---------------- device global scratch ----------------
__device__ float g_bufA[MM*CC];
__device__ float g_bufB[MM*CC];
__device__ uint32_t g_qkv[MM*FIVEC];    // packed bf16 hi|lo per element
__device__ float g_S[BB*HH*NT*NN];      // s1: fp32 S1; s2 overwrites with packed bf16 A
__device__ float g_part[2*4096];
__device__ float g_ms[2];
__device__ float g_pool[BB*NT*CC];
__device__ int   g_isI64;
__device__ uint4 g_xhi[288*4*1024];
__device__ uint4 g_xlo[288*4*1024];
__device__ uint4 g_whi[DEPTH*10*4*1024];
__device__ uint4 g_wlo[DEPTH*10*4*1024];

// ---------------- adj dtype detection ----------------
__global__ void detect_adj_kern(const unsigned int* __restrict__ a, int n) {
    __shared__ int any;
    if (threadIdx.x == 0) any = 0;
    __syncthreads();
    int nz = 0;
    for (int i = 1 + 2*threadIdx.x; i < n; i += 2*blockDim.x)
        nz |= (a[i] != 0u);
    if (nz) any = 1;
    __syncthreads();
    if (threadIdx.x == 0) g_isI64 = any ? 0 : 1;
}

// ---------------- embedding gather ----------------
__global__ void embed_kern(const int* __restrict__ adj,
                           const float* __restrict__ emb,
                           float* __restrict__ X) {
    int i64 = g_isI64;
    int total = MM * (CC/4);
    for (int t = blockIdx.x*blockDim.x + threadIdx.x; t < total;
         t += gridDim.x*blockDim.x) {
        int m = t >> 6;
        int c4 = t & 63;
        int a = i64 ? adj[2*m] : adj[m];
        float4 v = ((const float4*)emb)[a*(CC/4) + c4];
        ((float4*)X)[m*(CC/4) + c4] = v;
    }
}

// ---------------- global mean/std reduction (float4 loads; layer 0 only) ----------------
__global__ void red1_kern(const float4* __restrict__ X) {
    float s = 0.f, s2 = 0.f;
    for (int i = blockIdx.x*blockDim.x + threadIdx.x; i < MM*CC/4;
         i += gridDim.x*blockDim.x) {
        float4 v = X[i];
        s  += (v.x + v.y) + (v.z + v.w);
        s2 += (v.x*v.x + v.y*v.y) + (v.z*v.z + v.w*v.w);
    }
    __shared__ float sh1[256], sh2[256];
    int t = threadIdx.x;
    sh1[t] = s; sh2[t] = s2;
    __syncthreads();
    for (int o = 128; o; o >>= 1) {
        if (t < o) { sh1[t] += sh1[t+o]; sh2[t] += sh2[t+o]; }
        __syncthreads();
    }
    if (t == 0) { g_part[blockIdx.x] = sh1[0]; g_part[4096 + blockIdx.x] = sh2[0]; }
}

__global__ void red2_kern(int n) {
    __shared__ double sh1[256], sh2[256];
    int t = threadIdx.x;
    double s = 0.0, s2 = 0.0;
    for (int i = t; i < n; i += 256) { s += (double)g_part[i]; s2 += (double)g_part[4096+i]; }
    sh1[t] = s; sh2[t] = s2;
    __syncthreads();
    for (int o = 128; o; o >>= 1) {
        if (t < o) { sh1[t] += sh1[t+o]; sh2[t] += sh2[t+o]; }
        __syncthreads();
    }
    if (t == 0) {
        double nn = (double)MM * (double)CC;
        double mean = sh1[0] / nn;
        double var  = (sh2[0] - sh1[0]*sh1[0]/nn) / (nn - 1.0);
        g_ms[0] = (float)mean;
        g_ms[1] = (float)(1.0 / sqrt(var));
    }
}

// ---------------- bf16 split conversions for QKV (pre-swizzled tiles) ----------------
__global__ void convert_x_kern(const float* __restrict__ X) {
    int idx = blockIdx.x*blockDim.x + threadIdx.x;
    if (idx >= MM*32) return;
    float mean = g_ms[0], istd = g_ms[1];
    int m = idx >> 5, k8 = idx & 31;
    const float4* src = (const float4*)(X + (size_t)m*CC + k8*8);
    float4 v0 = src[0], v1 = src[1];
    float v[8] = {v0.x,v0.y,v0.z,v0.w,v1.x,v1.y,v1.z,v1.w};
    uint32_t hw[4], lw[4];
    #pragma unroll
    for (int j = 0; j < 4; j++)
        split2((v[2*j] - mean)*istd, (v[2*j+1] - mean)*istd, hw[j], lw[j]);
    int mt = m >> 7, r = m & 127, kc = k8 >> 3;
    uint32_t off = r*128 + (k8 & 7)*16;
    uint32_t sw = sw128(off);
    size_t tile = (size_t)(mt*4 + kc)*1024 + (sw >> 4);
    g_xhi[tile] = make_uint4(hw[0], hw[1], hw[2], hw[3]);
    g_xlo[tile] = make_uint4(lw[0], lw[1], lw[2], lw[3]);
}

__global__ void convert_w_kern(const float* __restrict__ W) {
    int idx = blockIdx.x*blockDim.x + threadIdx.x;
    if (idx >= DEPTH*FIVEC*32) return;
    int l = idx / (FIVEC*32);
    int rem = idx % (FIVEC*32);
    int n = rem >> 5, k8 = rem & 31;
    const float4* src = (const float4*)(W + (size_t)l*FIVEC*CC + (size_t)n*CC + k8*8);
    float4 v0 = src[0], v1 = src[1];
    float v[8] = {v0.x,v0.y,v0.z,v0.w,v1.x,v1.y,v1.z,v1.w};
    uint32_t hw[4], lw[4];
    #pragma unroll
    for (int j = 0; j < 4; j++)
        split2(v[2*j], v[2*j+1], hw[j], lw[j]);
    int nt = n >> 7, r = n & 127, kc = k8 >> 3;
    uint32_t off = r*128 + (k8 & 7)*16;
    uint32_t sw = sw128(off);
    size_t tile = (size_t)((l*10 + nt)*4 + kc)*1024 + (sw >> 4);
    g_whi[tile] = make_uint4(hw[0], hw[1], hw[2], hw[3]);
    g_wlo[tile] = make_uint4(lw[0], lw[1], lw[2], lw[3]);
}

// ---------------- QKV GEMM via mma.sync bf16; packed-bf16 epilogue ----------------
#define SM_QKV 65536
__global__ void __launch_bounds__(256, 2)
qkv_mma_kern(int layer) {
    extern __shared__ char smem[];
    uint32_t sb = smem_u32(smem);
    int t = threadIdx.x, lane = t & 31, wid = t >> 5;
    int mt = blockIdx.x, ntile = blockIdx.y;
    int wm = wid & 1, wn = wid >> 1;

    float acc[4][4][4];
    #pragma unroll
    for (int a = 0; a < 4; a++)
        #pragma unroll
        for (int b = 0; b < 4; b++)
            #pragma unroll
            for (int c = 0; c < 4; c++) acc[a][b][c] = 0.f;

    auto issue_copy = [&](int c) {
        int s = c & 1;
        int akc = (c < 4) ? c : ((c < 8) ? c - 4 : c - 8);
        const uint4* Ap = ((c >= 4 && c < 8) ? g_xlo : g_xhi) + (size_t)(mt*4 + akc)*1024;
        int bkc = (c < 8) ? (c & 3) : (c - 8);
        const uint4* Bp = ((c < 8) ? g_whi : g_wlo) + (size_t)((layer*10 + ntile)*4 + bkc)*1024;
        uint32_t sa = sb + s*32768;
        #pragma unroll
        for (int i = 0; i < 4; i++)
            cp_async16(sa + (t + i*256)*16, Ap + t + i*256);
        uint32_t sbB = sa + 16384;
        #pragma unroll
        for (int i = 0; i < 4; i++)
            cp_async16(sbB + (t + i*256)*16, Bp + t + i*256);
        cp_commit();
    };

    issue_copy(0);
    #pragma unroll 1
    for (int c = 0; c < 12; c++) {
        int s = c & 1;
        if (c < 11) { issue_copy(c + 1); cp_wait<1>(); }
        else        { cp_wait<0>(); }
        __syncthreads();
        uint32_t Ab = sb + s*32768;
        uint32_t Bb = Ab + 16384;
        #pragma unroll
        for (int ks = 0; ks < 4; ks++) {
            uint32_t afr[4][4];
            #pragma unroll
            for (int mf = 0; mf < 4; mf++) {
                uint32_t off = (uint32_t)(wm*64 + mf*16 + (lane & 15))*128
                             + ks*32 + (lane >> 4)*16;
                ldsm_x4(afr[mf], Ab + sw128(off));
            }
            uint32_t bfr[4][2];
            #pragma unroll
            for (int nf = 0; nf < 4; nf++) {
                uint32_t off = (uint32_t)(wn*32 + nf*8 + (lane & 7))*128
                             + ks*32 + ((lane >> 3) & 1)*16;
                ldsm_x2(bfr[nf], Bb + sw128(off));
            }
            #pragma unroll
            for (int mf = 0; mf < 4; mf++)
                #pragma unroll
                for (int nf = 0; nf < 4; nf++)
                    mma16816(acc[mf][nf], afr[mf], bfr[nf]);
        }
        __syncthreads();
    }
    int rbase = mt*128 + wm*64 + (lane >> 2);
    int cbase = ntile*128 + wn*32 + (lane & 3)*2;
    #pragma unroll
    for (int mf = 0; mf < 4; mf++) {
        #pragma unroll
        for (int nf = 0; nf < 4; nf++) {
            size_t o0 = (size_t)(rbase + mf*16)*FIVEC + cbase + nf*8;
            *(uint2*)&g_qkv[o0] =
                make_uint2(elem_pack(acc[mf][nf][0]), elem_pack(acc[mf][nf][1]));
            *(uint2*)&g_qkv[o0 + 8*FIVEC] =
                make_uint2(elem_pack(acc[mf][nf][2]), elem_pack(acc[mf][nf][3]));
        }
    }
}

// ================= tensor-core attention =================
__device__ __forceinline__ void qk_gemm_3pass(uint32_t sb, uint32_t AHI, uint32_t ALO,
                                              uint32_t BHI, uint32_t BLO,
                                              int lane, int wm, int wn,
                                              float acc[3][3][4]) {
    uint32_t pa[3] = {AHI, ALO, AHI};
    uint32_t pb[3] = {BHI, BHI, BLO};
    #pragma unroll
    for (int ps = 0; ps < 3; ps++) {
        uint32_t Ab = sb + pa[ps], Bb = sb + pb[ps];
        #pragma unroll
        for (int ks = 0; ks < 2; ks++) {
            uint32_t afr[3][4];
            #pragma unroll
            for (int mf = 0; mf < 3; mf++) {
                uint32_t off = (uint32_t)(wm*48 + mf*16 + (lane & 15))*128
                             + ks*32 + (lane >> 4)*16;
                ldsm_x4(afr[mf], Ab + sw128(off));
            }
            uint32_t bfr[3][2];
            #pragma unroll
            for (int nf = 0; nf < 3; nf++) {
                uint32_t off = (uint32_t)(wn*24 + nf*8 + (lane & 7))*128
                             + ks*32 + ((lane >> 3) & 1)*16;
                ldsm_x2(bfr[nf], Bb + sw128(off));
            }
            #pragma unroll
            for (int mf = 0; mf < 3; mf++)
                #pragma unroll
                for (int nf = 0; nf < 3; nf++)
                    mma16816(acc[mf][nf], afr[mf], bfr[nf]);
        }
    }
}

__device__ __forceinline__ void av_gemm_3pass(uint32_t sb,
                                              uint32_t AHI0, uint32_t AHI1,
                                              uint32_t ALO0, uint32_t ALO1,
                                              uint32_t VHI0, uint32_t VHI1,
                                              uint32_t VLO0, uint32_t VLO1,
                                              int lane, int wm, int wn,
                                              float acc2[3][4]) {
    uint32_t pa0[3] = {AHI0, ALO0, AHI0}, pa1[3] = {AHI1, ALO1, AHI1};
    uint32_t pv0[3] = {VHI0, VHI0, VLO0}, pv1[3] = {VHI1, VHI1, VLO1};
    #pragma unroll
    for (int ps = 0; ps < 3; ps++) {
        #pragma unroll
        for (int ch = 0; ch < 2; ch++) {
            uint32_t Ab = sb + (ch ? pa1[ps] : pa0[ps]);
            uint32_t Vb = sb + (ch ? pv1[ps] : pv0[ps]);
            int nks = ch ? 2 : 4;
            #pragma unroll
            for (int ks = 0; ks < 4; ks++) {
                if (ks >= nks) break;
                uint32_t afr[3][4];
                #pragma unroll
                for (int mf = 0; mf < 3; mf++) {
                    uint32_t off = (uint32_t)(wm*48 + mf*16 + (lane & 15))*128
                                 + ks*32 + (lane >> 4)*16;
                    ldsm_x4(afr[mf], Ab + sw128(off));
                }
                uint32_t bfr[2];
                {
                    uint32_t off = (uint32_t)(wn*8 + (lane & 7))*128
                                 + ks*32 + ((lane >> 3) & 1)*16;
                    ldsm_x2(bfr, Vb + sw128(off));
                }
                #pragma unroll
                for (int mf = 0; mf < 3; mf++)
                    mma16816(acc2[mf], afr[mf], bfr);
            }
        }
    }
}

// ---------------- s1: per (b,h,i) — S1 = Q·K1^T (fp32 out) ----------------
#define SM_S1 49152
__global__ void __launch_bounds__(256, 3)
s1_mma_kern() {
    extern __shared__ char smem[];
    uint32_t sb = smem_u32(smem);
    int t = threadIdx.x, lane = t & 31, wid = t >> 5;
    int wm = wid & 1, wn = wid >> 1;
    int bhi = blockIdx.x;
    int i = bhi % NT, bh = bhi / NT;
    int h = bh % HH, b = bh / HH;
    int baseQ = (b*NN + i*NT)*FIVEC + h*DD;
    int baseK = baseQ + CC;
    for (int idx = t; idx < 384; idx += 256) {
        int r = idx >> 2, g = idx & 3;
        uint32_t sw = sw128((uint32_t)(r*128 + g*16));
        packtile8(g_qkv + baseQ + (size_t)r*FIVEC + g*8, sb + sw,         sb + 12288 + sw);
        packtile8(g_qkv + baseK + (size_t)r*FIVEC + g*8, sb + 24576 + sw, sb + 36864 + sw);
    }
    __syncthreads();
    float acc[3][3][4];
    #pragma unroll
    for (int a = 0; a < 3; a++)
        #pragma unroll
        for (int bq = 0; bq < 3; bq++)
            #pragma unroll
            for (int c = 0; c < 4; c++) acc[a][bq][c] = 0.f;
    qk_gemm_3pass(sb, 0, 12288, 24576, 36864, lane, wm, wn, acc);
    size_t base = (size_t)(bh*NT + i) * NN;
    int rbase = wm*48 + (lane >> 2);
    int cbase = wn*24 + (lane & 3)*2;
    #pragma unroll
    for (int mf = 0; mf < 3; mf++) {
        #pragma unroll
        for (int nf = 0; nf < 3; nf++) {
            int row = rbase + mf*16, col = cbase + nf*8;
            *(float2*)&g_S[base + (size_t)row*NT + col]     = make_float2(acc[mf][nf][0], acc[mf][nf][1]);
            *(float2*)&g_S[base + (size_t)(row+8)*NT + col] = make_float2(acc[mf][nf][2], acc[mf][nf][3]);
        }
    }
}

// ---------------- s2: per (b,h,j) — GEMM1 + register softmax + packed A + A·V2 GEMM ----------------
#define SM_S2M 68608
__global__ void __launch_bounds__(256, 3)
s2_mma_kern(float* __restrict__ Xout) {
    extern __shared__ char smem[];
    uint32_t sb = smem_u32(smem);
    float* redmax = (float*)(smem + 65536);
    float* redsum = (float*)(smem + 67072);
    int t = threadIdx.x, lane = t & 31, wid = t >> 5;
    int wm = wid & 1, wn = wid >> 1;
    int bhj = blockIdx.x;
    int j = bhj % NT, bh = bhj / NT;
    int h = bh % HH, b = bh / HH;
    int baseQ = (b*NN + j)*FIVEC + h*DD;
    int baseK2 = baseQ + 2*CC;
    int baseV2 = baseQ + 4*CC;

    for (int idx = t; idx < 384; idx += 256) {
        int r = idx >> 2, g = idx & 3;
        uint32_t sw = sw128((uint32_t)(r*128 + g*16));
        packtile8(g_qkv + baseQ  + (size_t)r*NT*FIVEC + g*8, sb + sw,         sb + 12288 + sw);
        packtile8(g_qkv + baseK2 + (size_t)r*NT*FIVEC + g*8, sb + 24576 + sw, sb + 36864 + sw);
    }
    for (int idx = t; idx < 48*32; idx += 256) {
        int d = idx & 31, pp = idx >> 5;
        int p = pp*2;
        uint32_t e0 = __ldg(&g_qkv[baseV2 + (size_t)p*NT*FIVEC + d]);
        uint32_t e1 = __ldg(&g_qkv[baseV2 + (size_t)(p+1)*NT*FIVEC + d]);
        uint32_t hw = __byte_perm(e0, e1, 0x5410);
        uint32_t lw = __byte_perm(e0, e1, 0x7632);
        uint32_t hbase = (p < 64) ? 49152u : 53248u;
        uint32_t lbase = (p < 64) ? 57344u : 61440u;
        uint32_t off = (uint32_t)d*128 + (uint32_t)((p < 64) ? p : p - 64)*2;
        uint32_t sw = sw128(off);
        sts32(sb + hbase + sw, hw);
        sts32(sb + lbase + sw, lw);
    }
    __syncthreads();
    float acc[3][3][4];
    #pragma unroll
    for (int a = 0; a < 3; a++)
        #pragma unroll
        for (int bq = 0; bq < 3; bq++)
            #pragma unroll
            for (int c = 0; c < 4; c++) acc[a][bq][c] = 0.f;
    qk_gemm_3pass(sb, 0, 12288, 24576, 36864, lane, wm, wn, acc);

    size_t sBase = (size_t)bh * NT * NN + (size_t)j * NT;
    int rbase = wm*48 + (lane >> 2);
    int cbase = wn*24 + (lane & 3)*2;
    #pragma unroll
    for (int mf = 0; mf < 3; mf++) {
        int r0 = rbase + mf*16;
        #pragma unroll
        for (int nf = 0; nf < 3; nf++) {
            int col = cbase + nf*8;
            float2 s1a = __ldg((const float2*)&g_S[sBase + (size_t)r0*NN + col]);
            float2 s1b = __ldg((const float2*)&g_S[sBase + (size_t)(r0+8)*NN + col]);
            acc[mf][nf][0] = (acc[mf][nf][0] + s1a.x) * SCALE_L2E;
            acc[mf][nf][1] = (acc[mf][nf][1] + s1a.y) * SCALE_L2E;
            acc[mf][nf][2] = (acc[mf][nf][2] + s1b.x) * SCALE_L2E;
            acc[mf][nf][3] = (acc[mf][nf][3] + s1b.y) * SCALE_L2E;
        }
    }
    float m0[3], m1[3];
    #pragma unroll
    for (int mf = 0; mf < 3; mf++) {
        m0[mf] = -1e30f; m1[mf] = -1e30f;
        #pragma unroll
        for (int nf = 0; nf < 3; nf++) {
            m0[mf] = fmaxf(m0[mf], fmaxf(acc[mf][nf][0], acc[mf][nf][1]));
            m1[mf] = fmaxf(m1[mf], fmaxf(acc[mf][nf][2], acc[mf][nf][3]));
        }
        m0[mf] = fmaxf(m0[mf], __shfl_xor_sync(0xffffffffu, m0[mf], 1));
        m0[mf] = fmaxf(m0[mf], __shfl_xor_sync(0xffffffffu, m0[mf], 2));
        m1[mf] = fmaxf(m1[mf], __shfl_xor_sync(0xffffffffu, m1[mf], 1));
        m1[mf] = fmaxf(m1[mf], __shfl_xor_sync(0xffffffffu, m1[mf], 2));
    }
    if ((lane & 3) == 0) {
        #pragma unroll
        for (int mf = 0; mf < 3; mf++) {
            int r0 = rbase + mf*16;
            redmax[r0*4 + wn]     = m0[mf];
            redmax[(r0+8)*4 + wn] = m1[mf];
        }
    }
    __syncthreads();
    float s0[3], s1[3];
    #pragma unroll
    for (int mf = 0; mf < 3; mf++) {
        int r0 = rbase + mf*16;
        float rm0 = fmaxf(fmaxf(redmax[r0*4], redmax[r0*4+1]),
                          fmaxf(redmax[r0*4+2], redmax[r0*4+3]));
        float rm1 = fmaxf(fmaxf(redmax[(r0+8)*4], redmax[(r0+8)*4+1]),
                          fmaxf(redmax[(r0+8)*4+2], redmax[(r0+8)*4+3]));
        s0[mf] = 0.f; s1[mf] = 0.f;
        #pragma unroll
        for (int nf = 0; nf < 3; nf++) {
            acc[mf][nf][0] = ex2f(acc[mf][nf][0] - rm0);
            acc[mf][nf][1] = ex2f(acc[mf][nf][1] - rm0);
            acc[mf][nf][2] = ex2f(acc[mf][nf][2] - rm1);
            acc[mf][nf][3] = ex2f(acc[mf][nf][3] - rm1);
            s0[mf] += acc[mf][nf][0] + acc[mf][nf][1];
            s1[mf] += acc[mf][nf][2] + acc[mf][nf][3];
        }
        s0[mf] += __shfl_xor_sync(0xffffffffu, s0[mf], 1);
        s0[mf] += __shfl_xor_sync(0xffffffffu, s0[mf], 2);
        s1[mf] += __shfl_xor_sync(0xffffffffu, s1[mf], 1);
        s1[mf] += __shfl_xor_sync(0xffffffffu, s1[mf], 2);
    }
    if ((lane & 3) == 0) {
        #pragma unroll
        for (int mf = 0; mf < 3; mf++) {
            int r0 = rbase + mf*16;
            redsum[r0*4 + wn]     = s0[mf];
            redsum[(r0+8)*4 + wn] = s1[mf];
        }
    }
    __syncthreads();
    uint2* gS2 = (uint2*)g_S;
    #pragma unroll
    for (int mf = 0; mf < 3; mf++) {
        int r0 = rbase + mf*16;
        float inv0 = 1.f / ((redsum[r0*4] + redsum[r0*4+1]) +
                            (redsum[r0*4+2] + redsum[r0*4+3]));
        float inv1 = 1.f / ((redsum[(r0+8)*4] + redsum[(r0+8)*4+1]) +
                            (redsum[(r0+8)*4+2] + redsum[(r0+8)*4+3]));
        #pragma unroll
        for (int nf = 0; nf < 3; nf++) {
            int col = cbase + nf*8;
            uint32_t e0 = elem_pack(acc[mf][nf][0]*inv0);
            uint32_t e1 = elem_pack(acc[mf][nf][1]*inv0);
            uint32_t e2 = elem_pack(acc[mf][nf][2]*inv1);
            uint32_t e3 = elem_pack(acc[mf][nf][3]*inv1);
            gS2[(sBase + (size_t)r0*NN + col) >> 1]     = make_uint2(e0, e1);
            gS2[(sBase + (size_t)(r0+8)*NN + col) >> 1] = make_uint2(e2, e3);
            int ch = col < 64;
            uint32_t hb = ch ? 0u : 12288u;
            uint32_t lb = ch ? 24576u : 36864u;
            uint32_t off0 = (uint32_t)r0*128 + (uint32_t)(ch ? col : col - 64)*2;
            uint32_t off1 = off0 + 1024;
            sts32(sb + hb + sw128(off0), __byte_perm(e0, e1, 0x5410));
            sts32(sb + lb + sw128(off0), __byte_perm(e0, e1, 0x7632));
            sts32(sb + hb + sw128(off1), __byte_perm(e2, e3, 0x5410));
            sts32(sb + lb + sw128(off1), __byte_perm(e2, e3, 0x7632));
        }
    }
    __syncthreads();
    float acc2[3][4];
    #pragma unroll
    for (int a = 0; a < 3; a++)
        #pragma unroll
        for (int c = 0; c < 4; c++) acc2[a][c] = 0.f;
    av_gemm_3pass(sb, 0, 12288, 24576, 36864, 49152, 53248, 57344, 61440,
                  lane, wm, wn, acc2);
    {
        int col = wn*8 + (lane & 3)*2;
        #pragma unroll
        for (int mf = 0; mf < 3; mf++) {
            int row = rbase + mf*16;
            size_t o0 = (size_t)(b*NN + row*NT + j)*CC + h*DD + col;
            size_t o1 = (size_t)(b*NN + (row+8)*NT + j)*CC + h*DD + col;
            *(float2*)&Xout[o0] = make_float2(acc2[mf][0], acc2[mf][1]);
            *(float2*)&Xout[o1] = make_float2(acc2[mf][2], acc2[mf][3]);
        }
    }
}

// ---------------- o1: per (b,h,i) — O1 = A·V1 + RMW Xout + stats; final layer: fused pooling ----------------
#define SM_O1M 65536
__global__ void __launch_bounds__(256, 3)
o1_mma_kern(float* __restrict__ Xout, int last) {
    extern __shared__ char smem[];
    uint32_t sb = smem_u32(smem);
    int t = threadIdx.x, lane = t & 31, wid = t >> 5;
    int wm = wid & 1, wn = wid >> 1;
    int bhi = blockIdx.x;
    int i = bhi % NT, bh = bhi / NT;
    int h = bh % HH, b = bh / HH;
    size_t aBase = (size_t)(bh*NT + i) * NN;
    int baseV = (b*NN + i*NT)*FIVEC + 3*CC + h*DD;

    const uint32_t* gS32 = (const uint32_t*)g_S;
    for (int idx = t; idx < 96*12; idx += 256) {
        int r = idx / 12, g = idx % 12;
        uint32_t hbase = (g < 8) ? 0u : 12288u;
        uint32_t lbase = (g < 8) ? 24576u : 36864u;
        uint32_t off = (uint32_t)r*128 + (uint32_t)((g < 8) ? g : g - 8)*16;
        uint32_t sw = sw128(off);
        packtile8(gS32 + aBase + (size_t)r*NT + g*8, sb + hbase + sw, sb + lbase + sw);
    }
    for (int idx = t; idx < 48*32; idx += 256) {
        int d = idx & 31, pp = idx >> 5;
        int p = pp*2;
        uint32_t e0 = __ldg(&g_qkv[baseV + (size_t)p*FIVEC + d]);
        uint32_t e1 = __ldg(&g_qkv[baseV + (size_t)(p+1)*FIVEC + d]);
        uint32_t hw = __byte_perm(e0, e1, 0x5410);
        uint32_t lw = __byte_perm(e0, e1, 0x7632);
        uint32_t hbase = (p < 64) ? 49152u : 53248u;
        uint32_t lbase = (p < 64) ? 57344u : 61440u;
        uint32_t off = (uint32_t)d*128 + (uint32_t)((p < 64) ? p : p - 64)*2;
        uint32_t sw = sw128(off);
        sts32(sb + hbase + sw, hw);
        sts32(sb + lbase + sw, lw);
    }
    __syncthreads();
    float acc2[3][4];
    #pragma unroll
    for (int a = 0; a < 3; a++)
        #pragma unroll
        for (int c = 0; c < 4; c++) acc2[a][c] = 0.f;
    av_gemm_3pass(sb, 0, 12288, 24576, 36864, 49152, 53248, 57344, 61440,
                  lane, wm, wn, acc2);
    float ps = 0.f, ps2 = 0.f;
    float ce = 0.f, co = 0.f;       // per-thread column sums (for final pooling)
    {
        int rbase = wm*48 + (lane >> 2);
        int col = wn*8 + (lane & 3)*2;
        #pragma unroll
        for (int mf = 0; mf < 3; mf++) {
            int row = rbase + mf*16;   // j
            size_t o0 = (size_t)(b*NN + i*NT + row)*CC + h*DD + col;
            size_t o1 = (size_t)(b*NN + i*NT + row + 8)*CC + h*DD + col;
            float2 a0 = *(const float2*)&Xout[o0];
            float2 a1 = *(const float2*)&Xout[o1];
            float f0 = a0.x + acc2[mf][0], f1 = a0.y + acc2[mf][1];
            float f2 = a1.x + acc2[mf][2], f3 = a1.y + acc2[mf][3];
            if (!last) {
                *(float2*)&Xout[o0] = make_float2(f0, f1);
                *(float2*)&Xout[o1] = make_float2(f2, f3);
            }
            ps  += (f0 + f1) + (f2 + f3);
            ps2 += (f0*f0 + f1*f1) + (f2*f2 + f3*f3);
            ce += f0 + f2;
            co += f1 + f3;
        }
    }
    __syncthreads();
    if (last) {
        // fused pooling: sum over all 96 j for this CTA's 32 columns
        float* colsum = (float*)smem;
        if (t < 32) colsum[t] = 0.f;
        __syncthreads();
        int col = wn*8 + (lane & 3)*2;
        atomicAdd(&colsum[col], ce);
        atomicAdd(&colsum[col + 1], co);
        __syncthreads();
        if (t < 32)
            g_pool[(size_t)(b*NT + i)*CC + h*DD + t] = colsum[t];
        return;
    }
    float* red = (float*)smem;
    red[t] = ps; red[256 + t] = ps2;
    __syncthreads();
    #pragma unroll
    for (int o = 128; o; o >>= 1) {
        if (t < o) { red[t] += red[t+o]; red[256+t] += red[256+t+o]; }
        __syncthreads();
    }
    if (t == 0) {
        g_part[blockIdx.x]        = red[0];
        g_part[4096 + blockIdx.x] = red[256];
    }
}

// ---------------- head ----------------
__global__ void pool2_head_kern(const float* __restrict__ W,
                                const float* __restrict__ bias,
                                float* __restrict__ out) {
    int b = blockIdx.x;
    __shared__ float xb[CC];
    int c = threadIdx.x;
    float s = 0.f;
    for (int i = 0; i < NT; i++)
        s += g_pool[(b*NT + i)*CC + c];
    xb[c] = s * (1.f / (float)NN);
    __syncthreads();
    float acc = bias[c];
    #pragma unroll 8
    for (int ci = 0; ci < CC; ci++)
        acc += xb[ci] * W[c*CC + ci];
    out[b*CC + c] = acc;
}

// ---------------- launch ----------------
extern "C" void kernel_launch(void* const* d_in, const int* in_sizes, int n_in,
                              void* d_out, int out_size) {
    const int*   adj   = (const int*)d_in[0];
    const float* emb   = (const float*)d_in[1];
    const float* qkvw  = (const float*)d_in[2];
    const float* headw = (const float*)d_in[3];
    const float* headb = (const float*)d_in[4];
    float* out = (float*)d_out;

    float *bufA, *bufB;
    cudaGetSymbolAddress((void**)&bufA, g_bufA);
    cudaGetSymbolAddress((void**)&bufB, g_bufB);

    cudaFuncSetAttribute(qkv_mma_kern, cudaFuncAttributeMaxDynamicSharedMemorySize, SM_QKV);
    cudaFuncSetAttribute(s1_mma_kern,  cudaFuncAttributeMaxDynamicSharedMemorySize, SM_S1);
    cudaFuncSetAttribute(s2_mma_kern,  cudaFuncAttributeMaxDynamicSharedMemorySize, SM_S2M);
    cudaFuncSetAttribute(o1_mma_kern,  cudaFuncAttributeMaxDynamicSharedMemorySize, SM_O1M);

    detect_adj_kern<<<1, 256>>>((const unsigned int*)adj, BB*NN);
    embed_kern<<<1024, 256>>>(adj, emb, bufA);
    convert_w_kern<<<(DEPTH*FIVEC*32 + 255)/256, 256>>>(qkvw);

    for (int l = 0; l < DEPTH; l++) {
        float* cur = (l & 1) ? bufB : bufA;
        float* nxt = (l & 1) ? bufA : bufB;
        if (l == 0) {
            red1_kern<<<1024, 256>>>((const float4*)cur);
            red2_kern<<<1, 256>>>(1024);
        } else {
            red2_kern<<<1, 256>>>(BB*HH*NT);   // partials from previous o1
        }
        convert_x_kern<<<(MM*32 + 255)/256, 256>>>(cur);
        qkv_mma_kern<<<dim3(MM/128, FIVEC/128), 256, SM_QKV>>>(l);
        s1_mma_kern<<<BB*HH*NT, 256, SM_S1>>>();
        s2_mma_kern<<<BB*HH*NT, 256, SM_S2M>>>(nxt);
        o1_mma_kern<<<BB*HH*NT, 256, SM_O1M>>>(nxt, l == DEPTH - 1);
    }
    pool2_head_kern<<<BB, 256>>>(headw, headb, out);
}

// round 17
// speedup vs baseline: 1.0956x; 1.0067x over previous
#include <cuda_runtime.h>
#include <cuda_bf16.h>
#include <math.h>
#include <stdint.h>

// Problem constants
#define BB 4
#define NT 96
#define CC 256
#define HH 8
#define DD 32
#define NN (NT*NT)          // 9216
#define MM (BB*NN)          // 36864
#define FIVEC (5*CC)        // 1280
#define DEPTH 4
#define SCALE_L2E (8.83883476483184405556f * 1.44269504088896340736f)

__device__ __forceinline__ float ex2f(float x) {
    float r; asm("ex2.approx.ftz.f32 %0, %1;" : "=f"(r) : "f"(x)); return r;
}

// ---------------- base-ISA tensor helpers (sm_80+) ----------------
__device__ __forceinline__ uint32_t smem_u32(const void* p) {
    uint32_t a;
    asm("{ .reg .u64 t; cvta.to.shared.u64 t, %1; cvt.u32.u64 %0, t; }" : "=r"(a) : "l"(p));
    return a;
}
__device__ __forceinline__ void cp_async16(uint32_t saddr, const void* gaddr) {
    asm volatile("cp.async.cg.shared.global [%0], [%1], 16;" :: "r"(saddr), "l"(gaddr));
}
__device__ __forceinline__ void cp_commit() {
    asm volatile("cp.async.commit_group;" ::: "memory");
}
template <int N>
__device__ __forceinline__ void cp_wait() {
    asm volatile("cp.async.wait_group %0;" :: "n"(N) : "memory");
}
__device__ __forceinline__ void ldsm_x4(uint32_t* r, uint32_t addr) {
    asm volatile("ldmatrix.sync.aligned.m8n8.x4.shared.b16 {%0,%1,%2,%3}, [%4];"
                 : "=r"(r[0]), "=r"(r[1]), "=r"(r[2]), "=r"(r[3]) : "r"(addr));
}
__device__ __forceinline__ void ldsm_x2(uint32_t* r, uint32_t addr) {
    asm volatile("ldmatrix.sync.aligned.m8n8.x2.shared.b16 {%0,%1}, [%2];"
                 : "=r"(r[0]), "=r"(r[1]) : "r"(addr));
}
__device__ __forceinline__ void mma16816(float* d, const uint32_t* a, const uint32_t* b) {
    asm volatile(
        "mma.sync.aligned.m16n8k16.row.col.f32.bf16.bf16.f32 "
        "{%0,%1,%2,%3}, {%4,%5,%6,%7}, {%8,%9}, {%0,%1,%2,%3};"
        : "+f"(d[0]), "+f"(d[1]), "+f"(d[2]), "+f"(d[3])
        : "r"(a[0]), "r"(a[1]), "r"(a[2]), "r"(a[3]), "r"(b[0]), "r"(b[1]));
}
__device__ __forceinline__ uint32_t sw128(uint32_t off) {
    return off ^ ((off >> 3) & 0x70);
}
__device__ __forceinline__ void sts128(uint32_t addr, uint32_t a, uint32_t b, uint32_t c, uint32_t d) {
    asm volatile("st.shared.v4.b32 [%0], {%1,%2,%3,%4};" :: "r"(addr), "r"(a), "r"(b), "r"(c), "r"(d));
}
__device__ __forceinline__ void sts32(uint32_t addr, uint32_t a) {
    asm volatile("st.shared.b32 [%0], %1;" :: "r"(addr), "r"(a));
}
__device__ __forceinline__ uint32_t pack_bf2(__nv_bfloat16 a, __nv_bfloat16 b) {
    return (uint32_t)__bfloat16_as_ushort(a) | ((uint32_t)__bfloat16_as_ushort(b) << 16);
}
__device__ __forceinline__ void split2(float a, float b, uint32_t& hi, uint32_t& lo) {
    __nv_bfloat16 h0 = __float2bfloat16(a), h1 = __float2bfloat16(b);
    __nv_bfloat16 l0 = __float2bfloat16(a - __bfloat162float(h0));
    __nv_bfloat16 l1 = __float2bfloat16(b - __bfloat162float(h1));
    hi = pack_bf2(h0, h1); lo = pack_bf2(l0, l1);
}
// packed element: hi bf16 in low half, lo bf16 in high half
__device__ __forceinline__ uint32_t elem_pack(float x) {
    __nv_bfloat16 h = __float2bfloat16(x);
    __nv_bfloat16 l = __float2bfloat16(x - __bfloat162float(h));
    return (uint32_t)__bfloat16_as_ushort(h) | ((uint32_t)__bfloat16_as_ushort(l) << 16);
}
// 8 packed words (read-only cache) -> hi/lo bf16x2 tiles (pure PRMT)
__device__ __forceinline__ void packtile8(const uint32_t* src, uint32_t hiaddr, uint32_t loaddr) {
    uint4 q0 = __ldg((const uint4*)src);
    uint4 q1 = __ldg((const uint4*)(src + 4));
    uint32_t e[8] = {q0.x,q0.y,q0.z,q0.w,q1.x,q1.y,q1.z,q1.w};
    uint32_t hw[4], lw[4];
    #pragma unroll
    for (int jj = 0; jj < 4; jj++) {
        hw[jj] = __byte_perm(e[2*jj], e[2*jj+1], 0x5410);
        lw[jj] = __byte_perm(e[2*jj], e[2*jj+1], 0x7632);
    }
    sts128(hiaddr, hw[0], hw[1], hw[2], hw[3]);
    sts128(loaddr, lw[0], lw[1], lw[2], lw[3]);
}

// ---------------- device global scratch ----------------
__device__ float g_bufA[MM*CC];
__device__ float g_bufB[MM*CC];
__device__ uint32_t g_qkv[MM*FIVEC];    // packed bf16 hi|lo per element
__device__ float g_S[BB*HH*NT*NN];      // s1: fp32 S1; s2 overwrites with packed bf16 A
__device__ float g_part[2*4096];
__device__ float g_ms[2];
__device__ float g_pool[BB*NT*CC];
__device__ int   g_isI64;
__device__ uint4 g_xhi[288*4*1024];
__device__ uint4 g_xlo[288*4*1024];
__device__ uint4 g_whi[DEPTH*10*4*1024];
__device__ uint4 g_wlo[DEPTH*10*4*1024];

// ---------------- adj dtype detection ----------------
__global__ void detect_adj_kern(const unsigned int* __restrict__ a, int n) {
    __shared__ int any;
    if (threadIdx.x == 0) any = 0;
    __syncthreads();
    int nz = 0;
    for (int i = 1 + 2*threadIdx.x; i < n; i += 2*blockDim.x)
        nz |= (a[i] != 0u);
    if (nz) any = 1;
    __syncthreads();
    if (threadIdx.x == 0) g_isI64 = any ? 0 : 1;
}

// ---------------- embedding gather + fused layer-0 norm stats ----------------
__global__ void embed_kern(const int* __restrict__ adj,
                           const float* __restrict__ emb,
                           float* __restrict__ X) {
    int i64 = g_isI64;
    int total = MM * (CC/4);
    float s = 0.f, s2 = 0.f;
    for (int t = blockIdx.x*blockDim.x + threadIdx.x; t < total;
         t += gridDim.x*blockDim.x) {
        int m = t >> 6;
        int c4 = t & 63;
        int a = i64 ? adj[2*m] : adj[m];
        float4 v = ((const float4*)emb)[a*(CC/4) + c4];
        ((float4*)X)[m*(CC/4) + c4] = v;
        s  += (v.x + v.y) + (v.z + v.w);
        s2 += (v.x*v.x + v.y*v.y) + (v.z*v.z + v.w*v.w);
    }
    __shared__ float sh1[256], sh2[256];
    int t = threadIdx.x;
    sh1[t] = s; sh2[t] = s2;
    __syncthreads();
    for (int o = 128; o; o >>= 1) {
        if (t < o) { sh1[t] += sh1[t+o]; sh2[t] += sh2[t+o]; }
        __syncthreads();
    }
    if (t == 0) { g_part[blockIdx.x] = sh1[0]; g_part[4096 + blockIdx.x] = sh2[0]; }
}

__global__ void red2_kern(int n) {
    __shared__ double sh1[256], sh2[256];
    int t = threadIdx.x;
    double s = 0.0, s2 = 0.0;
    for (int i = t; i < n; i += 256) { s += (double)g_part[i]; s2 += (double)g_part[4096+i]; }
    sh1[t] = s; sh2[t] = s2;
    __syncthreads();
    for (int o = 128; o; o >>= 1) {
        if (t < o) { sh1[t] += sh1[t+o]; sh2[t] += sh2[t+o]; }
        __syncthreads();
    }
    if (t == 0) {
        double nn = (double)MM * (double)CC;
        double mean = sh1[0] / nn;
        double var  = (sh2[0] - sh1[0]*sh1[0]/nn) / (nn - 1.0);
        g_ms[0] = (float)mean;
        g_ms[1] = (float)(1.0 / sqrt(var));
    }
}

// ---------------- bf16 split conversions for QKV (pre-swizzled tiles) ----------------
__global__ void convert_x_kern(const float* __restrict__ X) {
    int idx = blockIdx.x*blockDim.x + threadIdx.x;
    if (idx >= MM*32) return;
    float mean = g_ms[0], istd = g_ms[1];
    int m = idx >> 5, k8 = idx & 31;
    const float4* src = (const float4*)(X + (size_t)m*CC + k8*8);
    float4 v0 = src[0], v1 = src[1];
    float v[8] = {v0.x,v0.y,v0.z,v0.w,v1.x,v1.y,v1.z,v1.w};
    uint32_t hw[4], lw[4];
    #pragma unroll
    for (int j = 0; j < 4; j++)
        split2((v[2*j] - mean)*istd, (v[2*j+1] - mean)*istd, hw[j], lw[j]);
    int mt = m >> 7, r = m & 127, kc = k8 >> 3;
    uint32_t off = r*128 + (k8 & 7)*16;
    uint32_t sw = sw128(off);
    size_t tile = (size_t)(mt*4 + kc)*1024 + (sw >> 4);
    g_xhi[tile] = make_uint4(hw[0], hw[1], hw[2], hw[3]);
    g_xlo[tile] = make_uint4(lw[0], lw[1], lw[2], lw[3]);
}

__global__ void convert_w_kern(const float* __restrict__ W) {
    int idx = blockIdx.x*blockDim.x + threadIdx.x;
    if (idx >= DEPTH*FIVEC*32) return;
    int l = idx / (FIVEC*32);
    int rem = idx % (FIVEC*32);
    int n = rem >> 5, k8 = rem & 31;
    const float4* src = (const float4*)(W + (size_t)l*FIVEC*CC + (size_t)n*CC + k8*8);
    float4 v0 = src[0], v1 = src[1];
    float v[8] = {v0.x,v0.y,v0.z,v0.w,v1.x,v1.y,v1.z,v1.w};
    uint32_t hw[4], lw[4];
    #pragma unroll
    for (int j = 0; j < 4; j++)
        split2(v[2*j], v[2*j+1], hw[j], lw[j]);
    int nt = n >> 7, r = n & 127, kc = k8 >> 3;
    uint32_t off = r*128 + (k8 & 7)*16;
    uint32_t sw = sw128(off);
    size_t tile = (size_t)((l*10 + nt)*4 + kc)*1024 + (sw >> 4);
    g_whi[tile] = make_uint4(hw[0], hw[1], hw[2], hw[3]);
    g_wlo[tile] = make_uint4(lw[0], lw[1], lw[2], lw[3]);
}

// ---------------- QKV GEMM via mma.sync bf16; packed-bf16 epilogue ----------------
#define SM_QKV 65536
__global__ void __launch_bounds__(256, 2)
qkv_mma_kern(int layer) {
    extern __shared__ char smem[];
    uint32_t sb = smem_u32(smem);
    int t = threadIdx.x, lane = t & 31, wid = t >> 5;
    int mt = blockIdx.x, ntile = blockIdx.y;
    int wm = wid & 1, wn = wid >> 1;

    float acc[4][4][4];
    #pragma unroll
    for (int a = 0; a < 4; a++)
        #pragma unroll
        for (int b = 0; b < 4; b++)
            #pragma unroll
            for (int c = 0; c < 4; c++) acc[a][b][c] = 0.f;

    auto issue_copy = [&](int c) {
        int s = c & 1;
        int akc = (c < 4) ? c : ((c < 8) ? c - 4 : c - 8);
        const uint4* Ap = ((c >= 4 && c < 8) ? g_xlo : g_xhi) + (size_t)(mt*4 + akc)*1024;
        int bkc = (c < 8) ? (c & 3) : (c - 8);
        const uint4* Bp = ((c < 8) ? g_whi : g_wlo) + (size_t)((layer*10 + ntile)*4 + bkc)*1024;
        uint32_t sa = sb + s*32768;
        #pragma unroll
        for (int i = 0; i < 4; i++)
            cp_async16(sa + (t + i*256)*16, Ap + t + i*256);
        uint32_t sbB = sa + 16384;
        #pragma unroll
        for (int i = 0; i < 4; i++)
            cp_async16(sbB + (t + i*256)*16, Bp + t + i*256);
        cp_commit();
    };

    issue_copy(0);
    #pragma unroll 1
    for (int c = 0; c < 12; c++) {
        int s = c & 1;
        if (c < 11) { issue_copy(c + 1); cp_wait<1>(); }
        else        { cp_wait<0>(); }
        __syncthreads();
        uint32_t Ab = sb + s*32768;
        uint32_t Bb = Ab + 16384;
        #pragma unroll
        for (int ks = 0; ks < 4; ks++) {
            uint32_t afr[4][4];
            #pragma unroll
            for (int mf = 0; mf < 4; mf++) {
                uint32_t off = (uint32_t)(wm*64 + mf*16 + (lane & 15))*128
                             + ks*32 + (lane >> 4)*16;
                ldsm_x4(afr[mf], Ab + sw128(off));
            }
            uint32_t bfr[4][2];
            #pragma unroll
            for (int nf = 0; nf < 4; nf++) {
                uint32_t off = (uint32_t)(wn*32 + nf*8 + (lane & 7))*128
                             + ks*32 + ((lane >> 3) & 1)*16;
                ldsm_x2(bfr[nf], Bb + sw128(off));
            }
            #pragma unroll
            for (int mf = 0; mf < 4; mf++)
                #pragma unroll
                for (int nf = 0; nf < 4; nf++)
                    mma16816(acc[mf][nf], afr[mf], bfr[nf]);
        }
        __syncthreads();
    }
    int rbase = mt*128 + wm*64 + (lane >> 2);
    int cbase = ntile*128 + wn*32 + (lane & 3)*2;
    #pragma unroll
    for (int mf = 0; mf < 4; mf++) {
        #pragma unroll
        for (int nf = 0; nf < 4; nf++) {
            size_t o0 = (size_t)(rbase + mf*16)*FIVEC + cbase + nf*8;
            *(uint2*)&g_qkv[o0] =
                make_uint2(elem_pack(acc[mf][nf][0]), elem_pack(acc[mf][nf][1]));
            *(uint2*)&g_qkv[o0 + 8*FIVEC] =
                make_uint2(elem_pack(acc[mf][nf][2]), elem_pack(acc[mf][nf][3]));
        }
    }
}

// ================= tensor-core attention =================
__device__ __forceinline__ void qk_gemm_3pass(uint32_t sb, uint32_t AHI, uint32_t ALO,
                                              uint32_t BHI, uint32_t BLO,
                                              int lane, int wm, int wn,
                                              float acc[3][3][4]) {
    uint32_t pa[3] = {AHI, ALO, AHI};
    uint32_t pb[3] = {BHI, BHI, BLO};
    #pragma unroll
    for (int ps = 0; ps < 3; ps++) {
        uint32_t Ab = sb + pa[ps], Bb = sb + pb[ps];
        #pragma unroll
        for (int ks = 0; ks < 2; ks++) {
            uint32_t afr[3][4];
            #pragma unroll
            for (int mf = 0; mf < 3; mf++) {
                uint32_t off = (uint32_t)(wm*48 + mf*16 + (lane & 15))*128
                             + ks*32 + (lane >> 4)*16;
                ldsm_x4(afr[mf], Ab + sw128(off));
            }
            uint32_t bfr[3][2];
            #pragma unroll
            for (int nf = 0; nf < 3; nf++) {
                uint32_t off = (uint32_t)(wn*24 + nf*8 + (lane & 7))*128
                             + ks*32 + ((lane >> 3) & 1)*16;
                ldsm_x2(bfr[nf], Bb + sw128(off));
            }
            #pragma unroll
            for (int mf = 0; mf < 3; mf++)
                #pragma unroll
                for (int nf = 0; nf < 3; nf++)
                    mma16816(acc[mf][nf], afr[mf], bfr[nf]);
        }
    }
}

__device__ __forceinline__ void av_gemm_3pass(uint32_t sb,
                                              uint32_t AHI0, uint32_t AHI1,
                                              uint32_t ALO0, uint32_t ALO1,
                                              uint32_t VHI0, uint32_t VHI1,
                                              uint32_t VLO0, uint32_t VLO1,
                                              int lane, int wm, int wn,
                                              float acc2[3][4]) {
    uint32_t pa0[3] = {AHI0, ALO0, AHI0}, pa1[3] = {AHI1, ALO1, AHI1};
    uint32_t pv0[3] = {VHI0, VHI0, VLO0}, pv1[3] = {VHI1, VHI1, VLO1};
    #pragma unroll
    for (int ps = 0; ps < 3; ps++) {
        #pragma unroll
        for (int ch = 0; ch < 2; ch++) {
            uint32_t Ab = sb + (ch ? pa1[ps] : pa0[ps]);
            uint32_t Vb = sb + (ch ? pv1[ps] : pv0[ps]);
            int nks = ch ? 2 : 4;
            #pragma unroll
            for (int ks = 0; ks < 4; ks++) {
                if (ks >= nks) break;
                uint32_t afr[3][4];
                #pragma unroll
                for (int mf = 0; mf < 3; mf++) {
                    uint32_t off = (uint32_t)(wm*48 + mf*16 + (lane & 15))*128
                                 + ks*32 + (lane >> 4)*16;
                    ldsm_x4(afr[mf], Ab + sw128(off));
                }
                uint32_t bfr[2];
                {
                    uint32_t off = (uint32_t)(wn*8 + (lane & 7))*128
                                 + ks*32 + ((lane >> 3) & 1)*16;
                    ldsm_x2(bfr, Vb + sw128(off));
                }
                #pragma unroll
                for (int mf = 0; mf < 3; mf++)
                    mma16816(acc2[mf], afr[mf], bfr);
            }
        }
    }
}

// ---------------- s1: per (b,h,i) — S1 = Q·K1^T (fp32 out) ----------------
#define SM_S1 49152
__global__ void __launch_bounds__(256, 3)
s1_mma_kern() {
    extern __shared__ char smem[];
    uint32_t sb = smem_u32(smem);
    int t = threadIdx.x, lane = t & 31, wid = t >> 5;
    int wm = wid & 1, wn = wid >> 1;
    int bhi = blockIdx.x;
    int i = bhi % NT, bh = bhi / NT;
    int h = bh % HH, b = bh / HH;
    int baseQ = (b*NN + i*NT)*FIVEC + h*DD;
    int baseK = baseQ + CC;
    for (int idx = t; idx < 384; idx += 256) {
        int r = idx >> 2, g = idx & 3;
        uint32_t sw = sw128((uint32_t)(r*128 + g*16));
        packtile8(g_qkv + baseQ + (size_t)r*FIVEC + g*8, sb + sw,         sb + 12288 + sw);
        packtile8(g_qkv + baseK + (size_t)r*FIVEC + g*8, sb + 24576 + sw, sb + 36864 + sw);
    }
    __syncthreads();
    float acc[3][3][4];
    #pragma unroll
    for (int a = 0; a < 3; a++)
        #pragma unroll
        for (int bq = 0; bq < 3; bq++)
            #pragma unroll
            for (int c = 0; c < 4; c++) acc[a][bq][c] = 0.f;
    qk_gemm_3pass(sb, 0, 12288, 24576, 36864, lane, wm, wn, acc);
    size_t base = (size_t)(bh*NT + i) * NN;
    int rbase = wm*48 + (lane >> 2);
    int cbase = wn*24 + (lane & 3)*2;
    #pragma unroll
    for (int mf = 0; mf < 3; mf++) {
        #pragma unroll
        for (int nf = 0; nf < 3; nf++) {
            int row = rbase + mf*16, col = cbase + nf*8;
            *(float2*)&g_S[base + (size_t)row*NT + col]     = make_float2(acc[mf][nf][0], acc[mf][nf][1]);
            *(float2*)&g_S[base + (size_t)(row+8)*NT + col] = make_float2(acc[mf][nf][2], acc[mf][nf][3]);
        }
    }
}

// ---------------- s2: per (b,h,j) — bh REVERSED for L2 producer/consumer locality ----------------
#define SM_S2M 68608
__global__ void __launch_bounds__(256, 3)
s2_mma_kern(float* __restrict__ Xout) {
    extern __shared__ char smem[];
    uint32_t sb = smem_u32(smem);
    float* redmax = (float*)(smem + 65536);
    float* redsum = (float*)(smem + 67072);
    int t = threadIdx.x, lane = t & 31, wid = t >> 5;
    int wm = wid & 1, wn = wid >> 1;
    int bhj = blockIdx.x;
    int j = bhj % NT;
    int bh = (BB*HH - 1) - (bhj / NT);   // reversed: read S1 most-recently-written first
    int h = bh % HH, b = bh / HH;
    int baseQ = (b*NN + j)*FIVEC + h*DD;
    int baseK2 = baseQ + 2*CC;
    int baseV2 = baseQ + 4*CC;

    for (int idx = t; idx < 384; idx += 256) {
        int r = idx >> 2, g = idx & 3;
        uint32_t sw = sw128((uint32_t)(r*128 + g*16));
        packtile8(g_qkv + baseQ  + (size_t)r*NT*FIVEC + g*8, sb + sw,         sb + 12288 + sw);
        packtile8(g_qkv + baseK2 + (size_t)r*NT*FIVEC + g*8, sb + 24576 + sw, sb + 36864 + sw);
    }
    for (int idx = t; idx < 48*32; idx += 256) {
        int d = idx & 31, pp = idx >> 5;
        int p = pp*2;
        uint32_t e0 = __ldg(&g_qkv[baseV2 + (size_t)p*NT*FIVEC + d]);
        uint32_t e1 = __ldg(&g_qkv[baseV2 + (size_t)(p+1)*NT*FIVEC + d]);
        uint32_t hw = __byte_perm(e0, e1, 0x5410);
        uint32_t lw = __byte_perm(e0, e1, 0x7632);
        uint32_t hbase = (p < 64) ? 49152u : 53248u;
        uint32_t lbase = (p < 64) ? 57344u : 61440u;
        uint32_t off = (uint32_t)d*128 + (uint32_t)((p < 64) ? p : p - 64)*2;
        uint32_t sw = sw128(off);
        sts32(sb + hbase + sw, hw);
        sts32(sb + lbase + sw, lw);
    }
    __syncthreads();
    float acc[3][3][4];
    #pragma unroll
    for (int a = 0; a < 3; a++)
        #pragma unroll
        for (int bq = 0; bq < 3; bq++)
            #pragma unroll
            for (int c = 0; c < 4; c++) acc[a][bq][c] = 0.f;
    qk_gemm_3pass(sb, 0, 12288, 24576, 36864, lane, wm, wn, acc);

    size_t sBase = (size_t)bh * NT * NN + (size_t)j * NT;
    int rbase = wm*48 + (lane >> 2);
    int cbase = wn*24 + (lane & 3)*2;
    #pragma unroll
    for (int mf = 0; mf < 3; mf++) {
        int r0 = rbase + mf*16;
        #pragma unroll
        for (int nf = 0; nf < 3; nf++) {
            int col = cbase + nf*8;
            float2 s1a = __ldg((const float2*)&g_S[sBase + (size_t)r0*NN + col]);
            float2 s1b = __ldg((const float2*)&g_S[sBase + (size_t)(r0+8)*NN + col]);
            acc[mf][nf][0] = (acc[mf][nf][0] + s1a.x) * SCALE_L2E;
            acc[mf][nf][1] = (acc[mf][nf][1] + s1a.y) * SCALE_L2E;
            acc[mf][nf][2] = (acc[mf][nf][2] + s1b.x) * SCALE_L2E;
            acc[mf][nf][3] = (acc[mf][nf][3] + s1b.y) * SCALE_L2E;
        }
    }
    float m0[3], m1[3];
    #pragma unroll
    for (int mf = 0; mf < 3; mf++) {
        m0[mf] = -1e30f; m1[mf] = -1e30f;
        #pragma unroll
        for (int nf = 0; nf < 3; nf++) {
            m0[mf] = fmaxf(m0[mf], fmaxf(acc[mf][nf][0], acc[mf][nf][1]));
            m1[mf] = fmaxf(m1[mf], fmaxf(acc[mf][nf][2], acc[mf][nf][3]));
        }
        m0[mf] = fmaxf(m0[mf], __shfl_xor_sync(0xffffffffu, m0[mf], 1));
        m0[mf] = fmaxf(m0[mf], __shfl_xor_sync(0xffffffffu, m0[mf], 2));
        m1[mf] = fmaxf(m1[mf], __shfl_xor_sync(0xffffffffu, m1[mf], 1));
        m1[mf] = fmaxf(m1[mf], __shfl_xor_sync(0xffffffffu, m1[mf], 2));
    }
    if ((lane & 3) == 0) {
        #pragma unroll
        for (int mf = 0; mf < 3; mf++) {
            int r0 = rbase + mf*16;
            redmax[r0*4 + wn]     = m0[mf];
            redmax[(r0+8)*4 + wn] = m1[mf];
        }
    }
    __syncthreads();
    float s0[3], s1[3];
    #pragma unroll
    for (int mf = 0; mf < 3; mf++) {
        int r0 = rbase + mf*16;
        float rm0 = fmaxf(fmaxf(redmax[r0*4], redmax[r0*4+1]),
                          fmaxf(redmax[r0*4+2], redmax[r0*4+3]));
        float rm1 = fmaxf(fmaxf(redmax[(r0+8)*4], redmax[(r0+8)*4+1]),
                          fmaxf(redmax[(r0+8)*4+2], redmax[(r0+8)*4+3]));
        s0[mf] = 0.f; s1[mf] = 0.f;
        #pragma unroll
        for (int nf = 0; nf < 3; nf++) {
            acc[mf][nf][0] = ex2f(acc[mf][nf][0] - rm0);
            acc[mf][nf][1] = ex2f(acc[mf][nf][1] - rm0);
            acc[mf][nf][2] = ex2f(acc[mf][nf][2] - rm1);
            acc[mf][nf][3] = ex2f(acc[mf][nf][3] - rm1);
            s0[mf] += acc[mf][nf][0] + acc[mf][nf][1];
            s1[mf] += acc[mf][nf][2] + acc[mf][nf][3];
        }
        s0[mf] += __shfl_xor_sync(0xffffffffu, s0[mf], 1);
        s0[mf] += __shfl_xor_sync(0xffffffffu, s0[mf], 2);
        s1[mf] += __shfl_xor_sync(0xffffffffu, s1[mf], 1);
        s1[mf] += __shfl_xor_sync(0xffffffffu, s1[mf], 2);
    }
    if ((lane & 3) == 0) {
        #pragma unroll
        for (int mf = 0; mf < 3; mf++) {
            int r0 = rbase + mf*16;
            redsum[r0*4 + wn]     = s0[mf];
            redsum[(r0+8)*4 + wn] = s1[mf];
        }
    }
    __syncthreads();
    uint2* gS2 = (uint2*)g_S;
    #pragma unroll
    for (int mf = 0; mf < 3; mf++) {
        int r0 = rbase + mf*16;
        float inv0 = 1.f / ((redsum[r0*4] + redsum[r0*4+1]) +
                            (redsum[r0*4+2] + redsum[r0*4+3]));
        float inv1 = 1.f / ((redsum[(r0+8)*4] + redsum[(r0+8)*4+1]) +
                            (redsum[(r0+8)*4+2] + redsum[(r0+8)*4+3]));
        #pragma unroll
        for (int nf = 0; nf < 3; nf++) {
            int col = cbase + nf*8;
            uint32_t e0 = elem_pack(acc[mf][nf][0]*inv0);
            uint32_t e1 = elem_pack(acc[mf][nf][1]*inv0);
            uint32_t e2 = elem_pack(acc[mf][nf][2]*inv1);
            uint32_t e3 = elem_pack(acc[mf][nf][3]*inv1);
            gS2[(sBase + (size_t)r0*NN + col) >> 1]     = make_uint2(e0, e1);
            gS2[(sBase + (size_t)(r0+8)*NN + col) >> 1] = make_uint2(e2, e3);
            int ch = col < 64;
            uint32_t hb = ch ? 0u : 12288u;
            uint32_t lb = ch ? 24576u : 36864u;
            uint32_t off0 = (uint32_t)r0*128 + (uint32_t)(ch ? col : col - 64)*2;
            uint32_t off1 = off0 + 1024;
            sts32(sb + hb + sw128(off0), __byte_perm(e0, e1, 0x5410));
            sts32(sb + lb + sw128(off0), __byte_perm(e0, e1, 0x7632));
            sts32(sb + hb + sw128(off1), __byte_perm(e2, e3, 0x5410));
            sts32(sb + lb + sw128(off1), __byte_perm(e2, e3, 0x7632));
        }
    }
    __syncthreads();
    float acc2[3][4];
    #pragma unroll
    for (int a = 0; a < 3; a++)
        #pragma unroll
        for (int c = 0; c < 4; c++) acc2[a][c] = 0.f;
    av_gemm_3pass(sb, 0, 12288, 24576, 36864, 49152, 53248, 57344, 61440,
                  lane, wm, wn, acc2);
    {
        int col = wn*8 + (lane & 3)*2;
        #pragma unroll
        for (int mf = 0; mf < 3; mf++) {
            int row = rbase + mf*16;
            size_t o0 = (size_t)(b*NN + row*NT + j)*CC + h*DD + col;
            size_t o1 = (size_t)(b*NN + (row+8)*NT + j)*CC + h*DD + col;
            *(float2*)&Xout[o0] = make_float2(acc2[mf][0], acc2[mf][1]);
            *(float2*)&Xout[o1] = make_float2(acc2[mf][2], acc2[mf][3]);
        }
    }
}

// ---------------- o1: per (b,h,i) — O1 = A·V1 + RMW Xout + stats; final layer: fused pooling ----------------
#define SM_O1M 65536
__global__ void __launch_bounds__(256, 3)
o1_mma_kern(float* __restrict__ Xout, int last) {
    extern __shared__ char smem[];
    uint32_t sb = smem_u32(smem);
    int t = threadIdx.x, lane = t & 31, wid = t >> 5;
    int wm = wid & 1, wn = wid >> 1;
    int bhi = blockIdx.x;
    int i = bhi % NT, bh = bhi / NT;
    int h = bh % HH, b = bh / HH;
    size_t aBase = (size_t)(bh*NT + i) * NN;
    int baseV = (b*NN + i*NT)*FIVEC + 3*CC + h*DD;

    const uint32_t* gS32 = (const uint32_t*)g_S;
    for (int idx = t; idx < 96*12; idx += 256) {
        int r = idx / 12, g = idx % 12;
        uint32_t hbase = (g < 8) ? 0u : 12288u;
        uint32_t lbase = (g < 8) ? 24576u : 36864u;
        uint32_t off = (uint32_t)r*128 + (uint32_t)((g < 8) ? g : g - 8)*16;
        uint32_t sw = sw128(off);
        packtile8(gS32 + aBase + (size_t)r*NT + g*8, sb + hbase + sw, sb + lbase + sw);
    }
    for (int idx = t; idx < 48*32; idx += 256) {
        int d = idx & 31, pp = idx >> 5;
        int p = pp*2;
        uint32_t e0 = __ldg(&g_qkv[baseV + (size_t)p*FIVEC + d]);
        uint32_t e1 = __ldg(&g_qkv[baseV + (size_t)(p+1)*FIVEC + d]);
        uint32_t hw = __byte_perm(e0, e1, 0x5410);
        uint32_t lw = __byte_perm(e0, e1, 0x7632);
        uint32_t hbase = (p < 64) ? 49152u : 53248u;
        uint32_t lbase = (p < 64) ? 57344u : 61440u;
        uint32_t off = (uint32_t)d*128 + (uint32_t)((p < 64) ? p : p - 64)*2;
        uint32_t sw = sw128(off);
        sts32(sb + hbase + sw, hw);
        sts32(sb + lbase + sw, lw);
    }
    __syncthreads();
    float acc2[3][4];
    #pragma unroll
    for (int a = 0; a < 3; a++)
        #pragma unroll
        for (int c = 0; c < 4; c++) acc2[a][c] = 0.f;
    av_gemm_3pass(sb, 0, 12288, 24576, 36864, 49152, 53248, 57344, 61440,
                  lane, wm, wn, acc2);
    float ps = 0.f, ps2 = 0.f;
    float ce = 0.f, co = 0.f;
    {
        int rbase = wm*48 + (lane >> 2);
        int col = wn*8 + (lane & 3)*2;
        #pragma unroll
        for (int mf = 0; mf < 3; mf++) {
            int row = rbase + mf*16;   // j
            size_t o0 = (size_t)(b*NN + i*NT + row)*CC + h*DD + col;
            size_t o1 = (size_t)(b*NN + i*NT + row + 8)*CC + h*DD + col;
            float2 a0 = *(const float2*)&Xout[o0];
            float2 a1 = *(const float2*)&Xout[o1];
            float f0 = a0.x + acc2[mf][0], f1 = a0.y + acc2[mf][1];
            float f2 = a1.x + acc2[mf][2], f3 = a1.y + acc2[mf][3];
            if (!last) {
                *(float2*)&Xout[o0] = make_float2(f0, f1);
                *(float2*)&Xout[o1] = make_float2(f2, f3);
            }
            ps  += (f0 + f1) + (f2 + f3);
            ps2 += (f0*f0 + f1*f1) + (f2*f2 + f3*f3);
            ce += f0 + f2;
            co += f1 + f3;
        }
    }
    __syncthreads();
    if (last) {
        float* colsum = (float*)smem;
        if (t < 32) colsum[t] = 0.f;
        __syncthreads();
        int col = wn*8 + (lane & 3)*2;
        atomicAdd(&colsum[col], ce);
        atomicAdd(&colsum[col + 1], co);
        __syncthreads();
        if (t < 32)
            g_pool[(size_t)(b*NT + i)*CC + h*DD + t] = colsum[t];
        return;
    }
    float* red = (float*)smem;
    red[t] = ps; red[256 + t] = ps2;
    __syncthreads();
    #pragma unroll
    for (int o = 128; o; o >>= 1) {
        if (t < o) { red[t] += red[t+o]; red[256+t] += red[256+t+o]; }
        __syncthreads();
    }
    if (t == 0) {
        g_part[blockIdx.x]        = red[0];
        g_part[4096 + blockIdx.x] = red[256];
    }
}

// ---------------- head ----------------
__global__ void pool2_head_kern(const float* __restrict__ W,
                                const float* __restrict__ bias,
                                float* __restrict__ out) {
    int b = blockIdx.x;
    __shared__ float xb[CC];
    int c = threadIdx.x;
    float s = 0.f;
    for (int i = 0; i < NT; i++)
        s += g_pool[(b*NT + i)*CC + c];
    xb[c] = s * (1.f / (float)NN);
    __syncthreads();
    float acc = bias[c];
    #pragma unroll 8
    for (int ci = 0; ci < CC; ci++)
        acc += xb[ci] * W[c*CC + ci];
    out[b*CC + c] = acc;
}

// ---------------- launch ----------------
extern "C" void kernel_launch(void* const* d_in, const int* in_sizes, int n_in,
                              void* d_out, int out_size) {
    const int*   adj   = (const int*)d_in[0];
    const float* emb   = (const float*)d_in[1];
    const float* qkvw  = (const float*)d_in[2];
    const float* headw = (const float*)d_in[3];
    const float* headb = (const float*)d_in[4];
    float* out = (float*)d_out;

    float *bufA, *bufB;
    cudaGetSymbolAddress((void**)&bufA, g_bufA);
    cudaGetSymbolAddress((void**)&bufB, g_bufB);

    cudaFuncSetAttribute(qkv_mma_kern, cudaFuncAttributeMaxDynamicSharedMemorySize, SM_QKV);
    cudaFuncSetAttribute(s1_mma_kern,  cudaFuncAttributeMaxDynamicSharedMemorySize, SM_S1);
    cudaFuncSetAttribute(s2_mma_kern,  cudaFuncAttributeMaxDynamicSharedMemorySize, SM_S2M);
    cudaFuncSetAttribute(o1_mma_kern,  cudaFuncAttributeMaxDynamicSharedMemorySize, SM_O1M);

    detect_adj_kern<<<1, 256>>>((const unsigned int*)adj, BB*NN);
    embed_kern<<<1024, 256>>>(adj, emb, bufA);     // fused layer-0 stats
    convert_w_kern<<<(DEPTH*FIVEC*32 + 255)/256, 256>>>(qkvw);

    for (int l = 0; l < DEPTH; l++) {
        float* cur = (l & 1) ? bufB : bufA;
        float* nxt = (l & 1) ? bufA : bufB;
        red2_kern<<<1, 256>>>(l == 0 ? 1024 : BB*HH*NT);
        convert_x_kern<<<(MM*32 + 255)/256, 256>>>(cur);
        qkv_mma_kern<<<dim3(MM/128, FIVEC/128), 256, SM_QKV>>>(l);
        s1_mma_kern<<<BB*HH*NT, 256, SM_S1>>>();
        s2_mma_kern<<<BB*HH*NT, 256, SM_S2M>>>(nxt);
        o1_mma_kern<<<BB*HH*NT, 256, SM_O1M>>>(nxt, l == DEPTH - 1);
    }
    pool2_head_kern<<<BB, 256>>>(headw, headb, out);
}